// round 15
// baseline (speedup 1.0000x reference)
#include <cuda_runtime.h>
#include <cuda_bf16.h>
#include <cuda_fp16.h>
#include <cfloat>
#include <cmath>
#include <cstdint>

// ---------------------------------------------------------------------------
// Problem constants
// ---------------------------------------------------------------------------
constexpr int B_  = 32;
constexpr int N_  = 513;      // G+1 tokens
constexpr int C_  = 384;
constexpr int H_  = 6;
constexpr int G_  = 512;
constexpr int V_  = 6;
constexpr int NC_ = 2048;     // N_CLUSTERS
constexpr int D2_ = 6272;     // B*GRID*GRID
constexpr int T_  = B_ * N_;  // 16416 tokens
constexpr int TG_ = B_ * G_;  // 16384 patch tokens
constexpr int NSLOT_ = 7;     // 6 views + cluster
constexpr float EPS_ = 1e-5f;

// ---------------------------------------------------------------------------
// Scratch (static device globals; no runtime allocation)
// ---------------------------------------------------------------------------
__device__ __half g_tv   [V_ * D2_ * C_];  // pooled t per view (fp16)
__device__ __half g_t3   [NC_ * C_];       // pooled t for cluster path (fp16)
__device__ float g_stats[NSLOT_ * 2 * C_];
__device__ float g_bns  [NSLOT_ * C_];     // BN scale per slot
__device__ float g_bnb  [NSLOT_ * C_];     // BN shift per slot
__device__ float g_bcorr[V_ * C_];

// CSR for segment pooling (slot 0..5 = views over fgi, slot 6 = cluster)
__device__ int g_cnt [NSLOT_ * D2_];
__device__ int g_off [NSLOT_ * D2_];
__device__ int g_fill[NSLOT_ * D2_];
__device__ int g_list[NSLOT_ * TG_];
// mask compaction
__device__ int g_mcnt [V_];
__device__ int g_mrows[V_ * TG_];
__device__ int g_mpos [V_ * TG_];

// bf16/fp16 staging
__device__ __nv_bfloat16 g_ah[T_ * C_];            // LN out / attn out / fc2 out (bf16)
__device__ __half        g_zh[TG_ * C_];           // unit-gamma LN of patch rows (fp16)
__device__ __half        g_xpat[TG_ * C_];         // compact patch xout rows (fp16)
__device__ __half        g_hlocC[V_ * TG_ * C_];   // compacted per-view hloc (fp16)
__device__ __nv_bfloat16 g_qh[T_ * 3 * C_];        // qkv bf16
__device__ __nv_bfloat16 g_hh[T_ * 4 * C_];        // fc1 out bf16
__device__ __nv_bfloat16 g_wqkvT[3 * C_ * C_];
__device__ __nv_bfloat16 g_wprojT[C_ * C_];
__device__ __nv_bfloat16 g_wfc1T [4 * C_ * C_];
__device__ __nv_bfloat16 g_wfc2T [C_ * 4 * C_];
__device__ __half        g_wattnT[V_ * C_ * C_];   // fp16 view weights

// ---------------------------------------------------------------------------
// Portable PTX helpers (sm_80+ baseline)
// ---------------------------------------------------------------------------
__device__ __forceinline__ uint32_t smem_u32(const void* p) {
    uint32_t a;
    asm("{ .reg .u64 t; cvta.to.shared.u64 t, %1; cvt.u32.u64 %0, t; }" : "=r"(a) : "l"(p));
    return a;
}
__device__ __forceinline__ void cpa16(uint32_t dst, const void* src, int sz) {
    asm volatile("cp.async.cg.shared.global [%0], [%1], 16, %2;"
                 :: "r"(dst), "l"(src), "r"(sz) : "memory");
}
#define CPA_COMMIT() asm volatile("cp.async.commit_group;" ::: "memory")
#define CPA_WAIT1()  asm volatile("cp.async.wait_group 1;" ::: "memory")
#define CPA_WAIT0()  asm volatile("cp.async.wait_group 0;" ::: "memory")

__device__ __forceinline__ void ldm_x4(uint32_t* r, uint32_t addr) {
    asm volatile("ldmatrix.sync.aligned.m8n8.x4.shared.b16 {%0,%1,%2,%3}, [%4];"
                 : "=r"(r[0]), "=r"(r[1]), "=r"(r[2]), "=r"(r[3]) : "r"(addr));
}
__device__ __forceinline__ void ldm_x4_trans(uint32_t* r, uint32_t addr) {
    asm volatile("ldmatrix.sync.aligned.m8n8.x4.trans.shared.b16 {%0,%1,%2,%3}, [%4];"
                 : "=r"(r[0]), "=r"(r[1]), "=r"(r[2]), "=r"(r[3]) : "r"(addr));
}
__device__ __forceinline__ void mma_bf16(float* c, const uint32_t* a, uint32_t b0, uint32_t b1) {
    asm volatile("mma.sync.aligned.m16n8k16.row.col.f32.bf16.bf16.f32 "
                 "{%0,%1,%2,%3}, {%4,%5,%6,%7}, {%8,%9}, {%0,%1,%2,%3};"
                 : "+f"(c[0]), "+f"(c[1]), "+f"(c[2]), "+f"(c[3])
                 : "r"(a[0]), "r"(a[1]), "r"(a[2]), "r"(a[3]), "r"(b0), "r"(b1));
}
__device__ __forceinline__ void mma_f16(float* c, const uint32_t* a, uint32_t b0, uint32_t b1) {
    asm volatile("mma.sync.aligned.m16n8k16.row.col.f32.f16.f16.f32 "
                 "{%0,%1,%2,%3}, {%4,%5,%6,%7}, {%8,%9}, {%0,%1,%2,%3};"
                 : "+f"(c[0]), "+f"(c[1]), "+f"(c[2]), "+f"(c[3])
                 : "r"(a[0]), "r"(a[1]), "r"(a[2]), "r"(a[3]), "r"(b0), "r"(b1));
}
__device__ __forceinline__ uint32_t packbf(float lo, float hi) {
    uint32_t r;
    asm("cvt.rn.bf16x2.f32 %0, %1, %2;" : "=r"(r) : "f"(hi), "f"(lo));
    return r;
}
__device__ __forceinline__ uint32_t packhf(float lo, float hi) {
    uint32_t r;
    asm("cvt.rn.f16x2.f32 %0, %1, %2;" : "=r"(r) : "f"(hi), "f"(lo));
    return r;
}

// ---------------------------------------------------------------------------
// Math helpers
// ---------------------------------------------------------------------------
__device__ __forceinline__ float geluf(float x) {
    return 0.5f * x * (1.0f + erff(x * 0.70710678118654752f));
}
__device__ __forceinline__ float warpSum(float v) {
    #pragma unroll
    for (int o = 16; o > 0; o >>= 1) v += __shfl_xor_sync(0xffffffffu, v, o);
    return v;
}

// ---------------------------------------------------------------------------
// bf16 HMMA GEMM, 3-stage cp.async pipeline, single barrier per K-iter.
// ---------------------------------------------------------------------------
constexpr int BM = 128, BN = 128, BK = 32;
constexpr int LDA = BK + 8;
constexpr int STAGE_ELEMS = BM * LDA + BN * LDA;   // 10240 elems = 20480 B
constexpr int SMEM_DYN = 3 * STAGE_ELEMS * 2;      // 61440 B

__global__ __launch_bounds__(256, 2)
void tgemm_kernel(const __nv_bfloat16* __restrict__ Ah,
                  const __nv_bfloat16* __restrict__ Bh,
                  const float* __restrict__ bias, const float* __restrict__ ls,
                  float* __restrict__ CoutF, __nv_bfloat16* __restrict__ outH,
                  int M, int Nn, int K, int doGelu)
{
    extern __shared__ __nv_bfloat16 smext[];
    uint32_t sbase = smem_u32(smext);

    int tid = threadIdx.x, lane = tid & 31, wid = tid >> 5;
    int wm = wid & 1, wn = wid >> 1;
    int m0 = blockIdx.y * BM, n0 = blockIdx.x * BN;

    const int total = K >> 5;

    float c[4][4][4];
    #pragma unroll
    for (int mi = 0; mi < 4; mi++)
        #pragma unroll
        for (int ni = 0; ni < 4; ni++)
            #pragma unroll
            for (int e = 0; e < 4; e++) c[mi][ni][e] = 0.0f;

    auto loadTiles = [&](int it, int s) {
        int k0 = it * BK;
        uint32_t aOff = sbase + (uint32_t)(s * STAGE_ELEMS) * 2;
        uint32_t bOff = aOff + (uint32_t)(BM * LDA) * 2;
        #pragma unroll
        for (int r = 0; r < 2; r++) {
            int idx = tid + r * 256;
            int row = idx >> 2;
            int ch  = (idx & 3) * 8;
            int gr  = m0 + row;
            int grc = gr < M ? gr : 0;
            cpa16(aOff + (uint32_t)(row * LDA + ch) * 2,
                  Ah + (size_t)grc * K + k0 + ch, gr < M ? 16 : 0);
            cpa16(bOff + (uint32_t)(row * LDA + ch) * 2,
                  Bh + (size_t)(n0 + row) * K + k0 + ch, 16);
        }
    };

    loadTiles(0, 0);
    CPA_COMMIT();
    if (total > 1) { loadTiles(1, 1); CPA_COMMIT(); }

    for (int it = 0; it < total; it++) {
        if (it + 1 < total) { CPA_WAIT1(); } else { CPA_WAIT0(); }
        __syncthreads();
        if (it + 2 < total) { loadTiles(it + 2, (it + 2) % 3); CPA_COMMIT(); }

        int cur = it % 3;
        uint32_t aB = sbase + (uint32_t)(cur * STAGE_ELEMS) * 2;
        uint32_t bB = aB + (uint32_t)(BM * LDA) * 2;

        #pragma unroll
        for (int k16 = 0; k16 < 2; k16++) {
            uint32_t a[4][4];
            #pragma unroll
            for (int mi = 0; mi < 4; mi++) {
                uint32_t addr = aB + (uint32_t)((wm * 64 + mi * 16 + (lane & 15)) * LDA
                                                + k16 * 16 + (lane >> 4) * 8) * 2;
                ldm_x4(a[mi], addr);
            }
            uint32_t b[2][4];
            #pragma unroll
            for (int bt = 0; bt < 2; bt++) {
                uint32_t addr = bB + (uint32_t)((wn * 32 + bt * 16 + (lane & 7) + ((lane >> 4) * 8)) * LDA
                                                + k16 * 16 + ((lane >> 3) & 1) * 8) * 2;
                ldm_x4(b[bt], addr);
            }
            #pragma unroll
            for (int mi = 0; mi < 4; mi++)
                #pragma unroll
                for (int ni = 0; ni < 4; ni++) {
                    const uint32_t* bb = b[ni >> 1];
                    int off = (ni & 1) * 2;
                    mma_bf16(c[mi][ni], a[mi], bb[off], bb[off + 1]);
                }
        }
    }

    int group = lane >> 2, qid = lane & 3;
    #pragma unroll
    for (int mi = 0; mi < 4; mi++) {
        #pragma unroll
        for (int ni = 0; ni < 4; ni++) {
            int col = n0 + wn * 32 + ni * 8 + qid * 2;
            #pragma unroll
            for (int half = 0; half < 2; half++) {
                int row = m0 + wm * 64 + mi * 16 + group + half * 8;
                if (row < M) {
                    float v0 = c[mi][ni][half * 2 + 0];
                    float v1 = c[mi][ni][half * 2 + 1];
                    if (bias) { v0 += bias[col]; v1 += bias[col + 1]; }
                    if (doGelu) { v0 = geluf(v0); v1 = geluf(v1); }
                    if (outH) {
                        *(uint32_t*)(outH + (size_t)row * Nn + col) = packbf(v0, v1);
                    } else {
                        float* cp = CoutF + (size_t)row * Nn + col;
                        if (ls) { cp[0] += ls[col] * v0; cp[1] += ls[col + 1] * v1; }
                        else    { cp[0] = v0; cp[1] = v1; }
                    }
                }
            }
        }
    }
}

// ---------------------------------------------------------------------------
// Batched per-view GEMM, fp16 single-pass, masked-row compaction,
// 3-stage pipeline, fp16 output. grid (3, 128, V).
// ---------------------------------------------------------------------------
__global__ __launch_bounds__(256, 2)
void tgemm_views_kernel(const __half* __restrict__ Zh,
                        const __half* __restrict__ WAll,
                        const float* __restrict__ bcorr, const int* __restrict__ mcnt,
                        const int* __restrict__ mrows, __half* __restrict__ hlocC)
{
    int v = blockIdx.z;
    int M = mcnt[v];
    int m0 = blockIdx.y * BM;
    if (m0 >= M) return;
    int n0 = blockIdx.x * BN;

    const __half* Bw = WAll + (size_t)v * C_ * C_;
    const float* bias = bcorr + v * C_;
    const int* rlist = mrows + v * TG_;
    __half* Cout = hlocC + (size_t)v * TG_ * C_;
    const int K = C_;

    extern __shared__ __nv_bfloat16 smext[];
    uint32_t sbase = smem_u32(smext);

    int tid = threadIdx.x, lane = tid & 31, wid = tid >> 5;
    int wm = wid & 1, wn = wid >> 1;

    const int total = K >> 5;            // 12

    float c[4][4][4];
    #pragma unroll
    for (int mi = 0; mi < 4; mi++)
        #pragma unroll
        for (int ni = 0; ni < 4; ni++)
            #pragma unroll
            for (int e = 0; e < 4; e++) c[mi][ni][e] = 0.0f;

    auto loadTiles = [&](int it, int s) {
        int k0 = it * BK;
        uint32_t aOff = sbase + (uint32_t)(s * STAGE_ELEMS) * 2;
        uint32_t bOff = aOff + (uint32_t)(BM * LDA) * 2;
        #pragma unroll
        for (int r = 0; r < 2; r++) {
            int idx = tid + r * 256;
            int row = idx >> 2;
            int ch  = (idx & 3) * 8;
            int rr  = m0 + row;
            int gr  = rr < M ? rlist[rr] : 0;
            cpa16(aOff + (uint32_t)(row * LDA + ch) * 2,
                  Zh + (size_t)gr * K + k0 + ch, rr < M ? 16 : 0);
            cpa16(bOff + (uint32_t)(row * LDA + ch) * 2,
                  Bw + (size_t)(n0 + row) * K + k0 + ch, 16);
        }
    };

    loadTiles(0, 0);
    CPA_COMMIT();
    loadTiles(1, 1);
    CPA_COMMIT();

    for (int it = 0; it < total; it++) {
        if (it + 1 < total) { CPA_WAIT1(); } else { CPA_WAIT0(); }
        __syncthreads();
        if (it + 2 < total) { loadTiles(it + 2, (it + 2) % 3); CPA_COMMIT(); }

        int cur = it % 3;
        uint32_t aB = sbase + (uint32_t)(cur * STAGE_ELEMS) * 2;
        uint32_t bB = aB + (uint32_t)(BM * LDA) * 2;

        #pragma unroll
        for (int k16 = 0; k16 < 2; k16++) {
            uint32_t a[4][4];
            #pragma unroll
            for (int mi = 0; mi < 4; mi++) {
                uint32_t addr = aB + (uint32_t)((wm * 64 + mi * 16 + (lane & 15)) * LDA
                                                + k16 * 16 + (lane >> 4) * 8) * 2;
                ldm_x4(a[mi], addr);
            }
            uint32_t b[2][4];
            #pragma unroll
            for (int bt = 0; bt < 2; bt++) {
                uint32_t addr = bB + (uint32_t)((wn * 32 + bt * 16 + (lane & 7) + ((lane >> 4) * 8)) * LDA
                                                + k16 * 16 + ((lane >> 3) & 1) * 8) * 2;
                ldm_x4(b[bt], addr);
            }
            #pragma unroll
            for (int mi = 0; mi < 4; mi++)
                #pragma unroll
                for (int ni = 0; ni < 4; ni++) {
                    const uint32_t* bb = b[ni >> 1];
                    int off = (ni & 1) * 2;
                    mma_f16(c[mi][ni], a[mi], bb[off], bb[off + 1]);
                }
        }
    }

    int group = lane >> 2, qid = lane & 3;
    #pragma unroll
    for (int mi = 0; mi < 4; mi++) {
        #pragma unroll
        for (int ni = 0; ni < 4; ni++) {
            int col = n0 + wn * 32 + ni * 8 + qid * 2;
            #pragma unroll
            for (int half = 0; half < 2; half++) {
                int row = m0 + wm * 64 + mi * 16 + group + half * 8;
                if (row < M) {
                    float v0 = c[mi][ni][half * 2 + 0] + bias[col];
                    float v1 = c[mi][ni][half * 2 + 1] + bias[col + 1];
                    *(uint32_t*)(Cout + (size_t)row * C_ + col) = packhf(v0, v1);
                }
            }
        }
    }
}

// ---------------------------------------------------------------------------
// Flash attention, bf16 HMMA, 64q/128thr, 3-stage cp.async KV pipeline.
// Dynamic smem: [sQ | 3 x (sK | sV)], LDQK=72 halves per row.
// ---------------------------------------------------------------------------
constexpr int LDQK = 72;
constexpr int ATT_TILE_ELEMS = 64 * LDQK;                    // 4608 halves
constexpr int ATT_SMEM = (ATT_TILE_ELEMS * 7) * 2;           // 64512 B

__global__ __launch_bounds__(128)
void fattn_kernel(const __nv_bfloat16* __restrict__ qkv, __nv_bfloat16* __restrict__ outH)
{
    extern __shared__ __nv_bfloat16 satt[];
    __nv_bfloat16* sQ = satt;
    int tid = threadIdx.x, lane = tid & 31, wid = tid >> 5;
    int qt = blockIdx.x, h = blockIdx.y, b = blockIdx.z;
    size_t base = (size_t)b * N_ * 1152;
    uint32_t sqb = smem_u32(satt);

    // load Q tile (synchronous)
    #pragma unroll
    for (int it = 0; it < 4; it++) {
        int idx = tid + it * 128;
        int row = idx >> 3, seg = idx & 7;
        int qi = qt * 64 + row; if (qi > N_ - 1) qi = N_ - 1;
        *(uint4*)&sQ[row * LDQK + seg * 8] =
            *(const uint4*)(qkv + base + (size_t)qi * 1152 + h * 64 + seg * 8);
    }

    // async KV tile loader: stage s in 0..2
    auto loadKV = [&](int kt, int s) {
        uint32_t kOff = sqb + (uint32_t)((1 + 2 * s) * ATT_TILE_ELEMS) * 2;
        uint32_t vOff = kOff + (uint32_t)ATT_TILE_ELEMS * 2;
        #pragma unroll
        for (int it = 0; it < 4; it++) {
            int idx = tid + it * 128;
            int row = idx >> 3, seg = idx & 7;
            int kv = kt * 64 + row; if (kv > N_ - 1) kv = N_ - 1;
            const __nv_bfloat16* src = qkv + base + (size_t)kv * 1152 + 384 + h * 64 + seg * 8;
            cpa16(kOff + (uint32_t)(row * LDQK + seg * 8) * 2, src, 16);
            cpa16(vOff + (uint32_t)(row * LDQK + seg * 8) * 2, src + 384, 16);
        }
    };

    loadKV(0, 0);
    CPA_COMMIT();
    loadKV(1, 1);
    CPA_COMMIT();

    __syncthreads();   // Q visible to all warps
    uint32_t aQ[4][4];
    #pragma unroll
    for (int k16 = 0; k16 < 4; k16++) {
        uint32_t addr = sqb + (uint32_t)((wid * 16 + (lane & 15)) * LDQK
                                         + k16 * 16 + (lane >> 4) * 8) * 2;
        ldm_x4(aQ[k16], addr);
    }

    float o[8][4];
    #pragma unroll
    for (int ch = 0; ch < 8; ch++)
        #pragma unroll
        for (int e = 0; e < 4; e++) o[ch][e] = 0.0f;
    float m0 = -1e30f, m1 = -1e30f, l0 = 0.0f, l1 = 0.0f;
    int q2 = (lane & 3) * 2;

    for (int kt = 0; kt < 9; kt++) {
        if (kt + 1 < 9) { CPA_WAIT1(); } else { CPA_WAIT0(); }
        __syncthreads();
        if (kt + 2 < 9) { loadKV(kt + 2, (kt + 2) % 3); CPA_COMMIT(); }

        int cur = kt % 3;
        uint32_t skb = sqb + (uint32_t)((1 + 2 * cur) * ATT_TILE_ELEMS) * 2;
        uint32_t svb = skb + (uint32_t)ATT_TILE_ELEMS * 2;

        // S = Q K^T
        float s[8][4];
        #pragma unroll
        for (int ch = 0; ch < 8; ch++)
            #pragma unroll
            for (int e = 0; e < 4; e++) s[ch][e] = 0.0f;
        #pragma unroll
        for (int ng = 0; ng < 4; ng++) {
            #pragma unroll
            for (int k16 = 0; k16 < 4; k16++) {
                uint32_t bk[4];
                uint32_t addr = skb + (uint32_t)((ng * 16 + (lane & 7) + ((lane >> 4) * 8)) * LDQK
                                                 + k16 * 16 + ((lane >> 3) & 1) * 8) * 2;
                ldm_x4(bk, addr);
                mma_bf16(s[2 * ng],     aQ[k16], bk[0], bk[1]);
                mma_bf16(s[2 * ng + 1], aQ[k16], bk[2], bk[3]);
            }
        }

        float lm0 = -1e30f, lm1 = -1e30f;
        #pragma unroll
        for (int ch = 0; ch < 8; ch++) {
            int j = kt * 64 + ch * 8 + q2;
            #pragma unroll
            for (int e = 0; e < 4; e++) s[ch][e] *= 0.125f;
            if (j >= N_)     { s[ch][0] = -1e30f; s[ch][2] = -1e30f; }
            if (j + 1 >= N_) { s[ch][1] = -1e30f; s[ch][3] = -1e30f; }
            lm0 = fmaxf(lm0, fmaxf(s[ch][0], s[ch][1]));
            lm1 = fmaxf(lm1, fmaxf(s[ch][2], s[ch][3]));
        }
        lm0 = fmaxf(lm0, __shfl_xor_sync(0xffffffffu, lm0, 1));
        lm0 = fmaxf(lm0, __shfl_xor_sync(0xffffffffu, lm0, 2));
        lm1 = fmaxf(lm1, __shfl_xor_sync(0xffffffffu, lm1, 1));
        lm1 = fmaxf(lm1, __shfl_xor_sync(0xffffffffu, lm1, 2));
        float mn0 = fmaxf(m0, lm0), mn1 = fmaxf(m1, lm1);
        float c0f = __expf(m0 - mn0), c1f = __expf(m1 - mn1);
        l0 *= c0f; l1 *= c1f;
        #pragma unroll
        for (int ch = 0; ch < 8; ch++) {
            o[ch][0] *= c0f; o[ch][1] *= c0f; o[ch][2] *= c1f; o[ch][3] *= c1f;
        }
        uint32_t P[8][2];
        float ls0 = 0.0f, ls1 = 0.0f;
        #pragma unroll
        for (int ch = 0; ch < 8; ch++) {
            float p0 = __expf(s[ch][0] - mn0), p1 = __expf(s[ch][1] - mn0);
            float p2 = __expf(s[ch][2] - mn1), p3 = __expf(s[ch][3] - mn1);
            ls0 += p0 + p1; ls1 += p2 + p3;
            P[ch][0] = packbf(p0, p1);
            P[ch][1] = packbf(p2, p3);
        }
        ls0 += __shfl_xor_sync(0xffffffffu, ls0, 1);
        ls0 += __shfl_xor_sync(0xffffffffu, ls0, 2);
        ls1 += __shfl_xor_sync(0xffffffffu, ls1, 1);
        ls1 += __shfl_xor_sync(0xffffffffu, ls1, 2);
        l0 += ls0; l1 += ls1; m0 = mn0; m1 = mn1;

        // O += P V
        #pragma unroll
        for (int dg = 0; dg < 4; dg++) {
            #pragma unroll
            for (int k16 = 0; k16 < 4; k16++) {
                uint32_t bv[4];
                uint32_t addr = svb + (uint32_t)((k16 * 16 + (lane & 15)) * LDQK
                                                 + dg * 16 + (lane >> 4) * 8) * 2;
                ldm_x4_trans(bv, addr);
                uint32_t ap[4] = {P[2 * k16][0], P[2 * k16][1],
                                  P[2 * k16 + 1][0], P[2 * k16 + 1][1]};
                mma_bf16(o[2 * dg],     ap, bv[0], bv[1]);
                mma_bf16(o[2 * dg + 1], ap, bv[2], bv[3]);
            }
        }
    }

    float i0 = 1.0f / l0, i1 = 1.0f / l1;
    int g = lane >> 2;
    int r0 = qt * 64 + wid * 16 + g, r1 = r0 + 8;
    #pragma unroll
    for (int ch = 0; ch < 8; ch++) {
        int col = h * 64 + ch * 8 + q2;
        if (r0 < N_)
            *(uint32_t*)(outH + (size_t)(b * N_ + r0) * C_ + col) = packbf(o[ch][0] * i0, o[ch][1] * i0);
        if (r1 < N_)
            *(uint32_t*)(outH + (size_t)(b * N_ + r1) * C_ + col) = packbf(o[ch][2] * i1, o[ch][3] * i1);
    }
}

// ---------------------------------------------------------------------------
// Weight transpose: bf16 (main GEMMs) and fp16 w/ row scale (views)
// ---------------------------------------------------------------------------
__global__ void transW_kernel(const float* __restrict__ W,
                              __nv_bfloat16* __restrict__ hiT, int K, int N)
{
    __shared__ float t[32][33];
    int n0 = blockIdx.x * 32, k0 = blockIdx.y * 32;
    int tx = threadIdx.x, ty = threadIdx.y;
    #pragma unroll
    for (int r = 0; r < 4; r++)
        t[ty + 8 * r][tx] = W[(size_t)(k0 + ty + 8 * r) * N + n0 + tx];
    __syncthreads();
    #pragma unroll
    for (int r = 0; r < 4; r++) {
        int nl = ty + 8 * r;
        hiT[(size_t)(n0 + nl) * K + k0 + tx] = __float2bfloat16(t[tx][nl]);
    }
}

__global__ void transWh_kernel(const float* __restrict__ W, const float* __restrict__ g,
                               __half* __restrict__ outT, int K, int N)
{
    __shared__ float t[32][33];
    int n0 = blockIdx.x * 32, k0 = blockIdx.y * 32;
    int tx = threadIdx.x, ty = threadIdx.y;
    #pragma unroll
    for (int r = 0; r < 4; r++)
        t[ty + 8 * r][tx] = W[(size_t)(k0 + ty + 8 * r) * N + n0 + tx];
    __syncthreads();
    float gs = g[k0 + tx];
    #pragma unroll
    for (int r = 0; r < 4; r++) {
        int nl = ty + 8 * r;
        outT[(size_t)(n0 + nl) * K + k0 + tx] = __float2half_rn(t[tx][nl] * gs);
    }
}

// ---------------------------------------------------------------------------
__global__ void biascorr_kernel(const float* __restrict__ attnW, const float* __restrict__ nb,
                                const float* __restrict__ ab, float* __restrict__ bc)
{
    int v = blockIdx.y;
    int n = blockIdx.x * 128 + threadIdx.x;
    const float* W = attnW + (size_t)v * C_ * C_;
    const float* b = nb + v * C_;
    float s = 0.0f;
    for (int k = 0; k < C_; k++) s += b[k] * W[(size_t)k * C_ + n];
    bc[v * C_ + n] = ab[v * C_ + n] + s;
}

// ---------------------------------------------------------------------------
// CSR build + mask compaction
// ---------------------------------------------------------------------------
__global__ void hist_kernel(const int* __restrict__ fgi, const int* __restrict__ cluster,
                            int* __restrict__ cnt)
{
    int v = blockIdx.y;
    int r = blockIdx.x * 256 + threadIdx.x;
    if (r >= TG_) return;
    int idx = (v < 6) ? fgi[v * TG_ + r] : cluster[r];
    atomicAdd(&cnt[v * D2_ + idx], 1);
}

__global__ void scan_kernel(const int* __restrict__ cnt, int* __restrict__ off,
                            int* __restrict__ fill)
{
    int v = blockIdx.x;
    int R = (v == 6) ? NC_ : D2_;
    const int* c = cnt + v * D2_;
    int* o = off + v * D2_;
    int* f = fill + v * D2_;
    __shared__ int part[256];
    int tid = threadIdx.x;
    int per = (R + 255) / 256;
    int base = tid * per;
    int s = 0;
    for (int i = 0; i < per; i++) { int j = base + i; if (j < R) s += c[j]; }
    part[tid] = s;
    __syncthreads();
    if (tid == 0) {
        int acc = 0;
        for (int i = 0; i < 256; i++) { int t = part[i]; part[i] = acc; acc += t; }
    }
    __syncthreads();
    int acc = part[tid];
    for (int i = 0; i < per; i++) {
        int j = base + i;
        if (j < R) { o[j] = acc; f[j] = acc; acc += c[j]; }
    }
}

__global__ void fillcsr_kernel(const int* __restrict__ fgi, const int* __restrict__ cluster,
                               int* __restrict__ fill, int* __restrict__ list)
{
    int v = blockIdx.y;
    int r = blockIdx.x * 256 + threadIdx.x;
    if (r >= TG_) return;
    int idx = (v < 6) ? fgi[v * TG_ + r] : cluster[r];
    int p = atomicAdd(&fill[v * D2_ + idx], 1);
    list[v * TG_ + p] = r;
}

__global__ void maskfill_kernel(const int* __restrict__ maskp, int* __restrict__ mcnt,
                                int* __restrict__ mrows, int* __restrict__ mpos)
{
    int v = blockIdx.y;
    int r = blockIdx.x * 256 + threadIdx.x;
    if (r >= TG_) return;
    if (maskp[v * TG_ + r]) {
        int p = atomicAdd(&mcnt[v], 1);
        mrows[v * TG_ + p] = r;
        mpos[v * TG_ + r] = p;
    }
}

// ---------------------------------------------------------------------------
// Batched gather-pool: warp per segment, 4 segments per block, fp16 in/out.
// slotBase selects slot range: slot = blockIdx.y + slotBase.
// ---------------------------------------------------------------------------
__global__ __launch_bounds__(128)
void gatherB_kernel(const __half* __restrict__ xpat, const __half* __restrict__ hlocC,
                    const int* __restrict__ mpos,
                    const int* __restrict__ off, const int* __restrict__ cnt,
                    const int* __restrict__ list,
                    __half* __restrict__ tv, __half* __restrict__ t3, int slotBase)
{
    int slot = blockIdx.y + slotBase;
    int warp = threadIdx.x >> 5, lane = threadIdx.x & 31;
    int j = blockIdx.x * 4 + warp;
    int R = (slot == 6) ? NC_ : D2_;
    if (j >= R) return;
    int base = off[slot * D2_ + j];
    int k = cnt[slot * D2_ + j];
    const int* rows = list + slot * TG_ + base;
    const __half2* xp2 = (const __half2*)xpat;
    const __half2* hC2 = (const __half2*)(hlocC + (size_t)slot * TG_ * C_);
    const int* mp = mpos + slot * TG_;

    float mxx[6], mxy[6], sx[6], sy[6];
    #pragma unroll
    for (int kk = 0; kk < 6; kk++) { mxx[kk] = -FLT_MAX; mxy[kk] = -FLT_MAX; sx[kk] = 0.0f; sy[kk] = 0.0f; }

    for (int i = 0; i < k; i++) {
        int r = rows[i];
        const __half2* src = xp2 + (size_t)r * 192;
        int p = (slot < 6) ? mp[r] : -1;
        if (p >= 0) {
            const __half2* hp = hC2 + (size_t)p * 192;
            #pragma unroll
            for (int kk = 0; kk < 6; kk++) {
                float2 v = __half22float2(src[lane + 32 * kk]);
                float2 h = __half22float2(hp[lane + 32 * kk]);
                v.x += h.x; v.y += h.y;
                mxx[kk] = fmaxf(mxx[kk], v.x); mxy[kk] = fmaxf(mxy[kk], v.y);
                sx[kk] += v.x; sy[kk] += v.y;
            }
        } else {
            #pragma unroll
            for (int kk = 0; kk < 6; kk++) {
                float2 v = __half22float2(src[lane + 32 * kk]);
                mxx[kk] = fmaxf(mxx[kk], v.x); mxy[kk] = fmaxf(mxy[kk], v.y);
                sx[kk] += v.x; sy[kk] += v.y;
            }
        }
    }

    __half* tp = (slot == 6) ? (t3 + (size_t)j * C_)
                             : (tv + ((size_t)slot * D2_ + j) * C_);
    if (k > 0) {
        float inv = 1.0f / (float)k;
        #pragma unroll
        for (int kk = 0; kk < 6; kk++) {
            *(uint32_t*)(tp + 2 * (lane + 32 * kk)) =
                packhf(mxx[kk] + sx[kk] * inv, mxy[kk] + sy[kk] * inv);
        }
    } else {
        #pragma unroll
        for (int kk = 0; kk < 6; kk++)
            *(uint32_t*)(tp + 2 * (lane + 32 * kk)) = 0u;
    }
}

// ---------------------------------------------------------------------------
__global__ void seg_statsB_kernel(const __half* __restrict__ tv, const __half* __restrict__ t3,
                                  float* __restrict__ stat, int slotBase)
{
    int slot = blockIdx.y + slotBase;
    int R = (slot == 6) ? NC_ : D2_;
    const __half* t = (slot == 6) ? t3 : tv + (size_t)slot * D2_ * C_;
    float* st = stat + slot * 2 * C_;
    int c = threadIdx.x;  // 384
    int rows_per = (R + gridDim.x - 1) / gridDim.x;
    int r0 = blockIdx.x * rows_per;
    int r1 = r0 + rows_per; if (r1 > R) r1 = R;
    float s1 = 0.0f, s2 = 0.0f;
    for (int r = r0; r < r1; r++) {
        float v = __half2float(t[(size_t)r * C_ + c]);
        s1 += v; s2 += v * v;
    }
    atomicAdd(&st[c], s1);
    atomicAdd(&st[C_ + c], s2);
}

// ---------------------------------------------------------------------------
__global__ void bnparam_kernel(const float* __restrict__ stat,
                               const float* __restrict__ bn2d_g, const float* __restrict__ bn2d_b,
                               const float* __restrict__ bn3d_g, const float* __restrict__ bn3d_b,
                               float* __restrict__ bns, float* __restrict__ bnb)
{
    int slot = blockIdx.x;
    int c = threadIdx.x;
    int R = (slot == 6) ? NC_ : D2_;
    const float* st = stat + slot * 2 * C_;
    float mean = st[c] / (float)R;
    float var  = fmaxf(st[C_ + c] / (float)R - mean * mean, 0.0f);
    float g = (slot == 6) ? bn3d_g[c] : bn2d_g[slot * C_ + c];
    float b = (slot == 6) ? bn3d_b[c] : bn2d_b[slot * C_ + c];
    float sc = g * rsqrtf(var + EPS_);
    bns[slot * C_ + c] = sc;
    bnb[slot * C_ + c] = b - mean * sc;
}

// ---------------------------------------------------------------------------
// LayerNorm over C -> bf16
// ---------------------------------------------------------------------------
__global__ void ln_kernel(const float* __restrict__ in,
                          const float* __restrict__ gam,
                          const float* __restrict__ bet,
                          __nv_bfloat16* __restrict__ outHi)
{
    int r = blockIdx.x;
    int tid = threadIdx.x;   // 128
    const float* row = in + (size_t)r * C_;
    float v0 = row[tid], v1 = row[tid + 128], v2 = row[tid + 256];
    __shared__ float sh[256];
    sh[tid] = v0 + v1 + v2;
    sh[128 + tid] = v0 * v0 + v1 * v1 + v2 * v2;
    __syncthreads();
    #pragma unroll
    for (int o = 64; o > 0; o >>= 1) {
        if (tid < o) { sh[tid] += sh[tid + o]; sh[128 + tid] += sh[128 + tid + o]; }
        __syncthreads();
    }
    float mean = sh[0] / C_;
    float var  = fmaxf(sh[128] / C_ - mean * mean, 0.0f);
    float inv  = rsqrtf(var + EPS_);
    #pragma unroll
    for (int k = 0; k < 3; k++) {
        int c = tid + 128 * k;
        float vv = (k == 0) ? v0 : (k == 1) ? v1 : v2;
        float y = (vv - mean) * inv;
        y = y * gam[c] + bet[c];
        outHi[(size_t)r * C_ + c] = __float2bfloat16(y);
    }
}

// ---------------------------------------------------------------------------
// Fused adapter + residual + unit-gamma LN -> fp16 z + fp16 compact xpat.
// ---------------------------------------------------------------------------
__global__ void adapterln_kernel(const __nv_bfloat16* __restrict__ fc2out,
                                 const float* __restrict__ ls2,
                                 const float* __restrict__ dw, const float* __restrict__ db,
                                 const float* __restrict__ uw, const float* __restrict__ ub,
                                 float* __restrict__ xout, __half* __restrict__ zh,
                                 __half* __restrict__ xpat)
{
    int t = blockIdx.x;
    int tid = threadIdx.x;  // 128
    __shared__ float xf[C_];
    __shared__ float h16[16];
    __shared__ float sh[256];
    #pragma unroll
    for (int k = 0; k < 3; k++) {
        int c = tid + 128 * k;
        xf[c] = ls2[c] * __bfloat162float(fc2out[(size_t)t * C_ + c]);
    }
    __syncthreads();
    int wid = tid >> 5, lane = tid & 31;
    #pragma unroll
    for (int jj = 0; jj < 4; jj++) {
        int j = wid * 4 + jj;
        float p = 0.0f;
        #pragma unroll
        for (int k = 0; k < 12; k++) {
            int c = lane + 32 * k;
            p += xf[c] * dw[c * 16 + j];
        }
        p = warpSum(p);
        if (lane == 0) h16[j] = geluf(p + db[j]);
    }
    __syncthreads();
    float nv[3];
    float s1 = 0.0f, s2 = 0.0f;
    #pragma unroll
    for (int k = 0; k < 3; k++) {
        int c = tid + 128 * k;
        float a = ub[c];
        #pragma unroll
        for (int j = 0; j < 16; j++) a += h16[j] * uw[j * C_ + c];
        float v = xout[(size_t)t * C_ + c] + xf[c] + 0.5f * a;
        xout[(size_t)t * C_ + c] = v;
        nv[k] = v;
        s1 += v; s2 += v * v;
    }
    sh[tid] = s1; sh[128 + tid] = s2;
    __syncthreads();
    #pragma unroll
    for (int o = 64; o > 0; o >>= 1) {
        if (tid < o) { sh[tid] += sh[tid + o]; sh[128 + tid] += sh[128 + tid + o]; }
        __syncthreads();
    }
    int bb = t / N_, idx = t - bb * N_;
    if (idx == 0) return;               // CLS token: no z/xpat
    float mean = sh[0] / C_;
    float var  = fmaxf(sh[128] / C_ - mean * mean, 0.0f);
    float inv  = rsqrtf(var + EPS_);
    size_t zr = (size_t)(bb * G_ + idx - 1) * C_;
    #pragma unroll
    for (int k = 0; k < 3; k++) {
        int c = tid + 128 * k;
        zh[zr + c]   = __float2half_rn((nv[k] - mean) * inv);
        xpat[zr + c] = __float2half_rn(nv[k]);
    }
}

// ---------------------------------------------------------------------------
// Final fusion: BN+gelu applied on the fly from fp16 pooled tables.
// ---------------------------------------------------------------------------
__global__ void sims_kernel(float* __restrict__ xout, const int* __restrict__ cluster,
                            const int* __restrict__ fgi,
                            const __half* __restrict__ t3, const __half* __restrict__ tv,
                            const float* __restrict__ bns, const float* __restrict__ bnb)
{
    int gw = (blockIdx.x * blockDim.x + threadIdx.x) >> 5;
    int lane = threadIdx.x & 31;
    if (gw >= TG_) return;
    int r = gw;
    int bb = r >> 9, gg = r & 511;
    size_t tok = (size_t)(bb * N_ + 1 + gg) * C_;

    float xr[12];
    const __half* xp = t3 + (size_t)cluster[r] * C_;
    float nx = 0.0f;
    #pragma unroll
    for (int k = 0; k < 12; k++) {
        int c = lane + 32 * k;
        float y = geluf(__half2float(xp[c]) * bns[6 * C_ + c] + bnb[6 * C_ + c]);
        xr[k] = y; nx += y * y;
    }
    nx = warpSum(nx);
    float nrmx = fmaxf(sqrtf(nx), 1e-8f);

    float d2[6][12];
    float w[6];
    float wsum = 0.0f;
    #pragma unroll
    for (int v = 0; v < 6; v++) {
        int ij = fgi[v * TG_ + r];
        const __half* dp = tv + ((size_t)v * D2_ + ij) * C_;
        float dot = 0.0f, nd = 0.0f;
        #pragma unroll
        for (int k = 0; k < 12; k++) {
            int c = lane + 32 * k;
            float dv = geluf(__half2float(dp[c]) * bns[v * C_ + c] + bnb[v * C_ + c]);
            d2[v][k] = dv;
            dot += dv * xr[k];
            nd  += dv * dv;
        }
        dot = warpSum(dot);
        nd  = warpSum(nd);
        float cosv = dot / (fmaxf(sqrtf(nd), 1e-8f) * nrmx);
        w[v] = (cosv + 1.0f) * 0.5f;
        wsum += w[v];
    }
    float inv = 1.0f / wsum;
    #pragma unroll
    for (int k = 0; k < 12; k++) {
        float a = 0.0f;
        #pragma unroll
        for (int v = 0; v < 6; v++) a += w[v] * d2[v][k];
        xout[tok + lane + 32 * k] += a * inv;   // COEF_PRO = 1
    }
}

// ---------------------------------------------------------------------------
// Host launcher
// ---------------------------------------------------------------------------
static float* symF(const void* sym) { void* p = nullptr; cudaGetSymbolAddress(&p, sym); return (float*)p; }
static int*   symI(const void* sym) { void* p = nullptr; cudaGetSymbolAddress(&p, sym); return (int*)p; }
static __nv_bfloat16* symH(const void* sym) { void* p = nullptr; cudaGetSymbolAddress(&p, sym); return (__nv_bfloat16*)p; }
static __half* symX(const void* sym) { void* p = nullptr; cudaGetSymbolAddress(&p, sym); return (__half*)p; }

static void tgemm(const __nv_bfloat16* Ah, const __nv_bfloat16* Bh,
                  const float* bias, const float* ls, float* CoutF, __nv_bfloat16* outH,
                  int M, int Nn, int K, int doGelu)
{
    dim3 grid(Nn / 128, (M + 127) / 128);
    tgemm_kernel<<<grid, 256, SMEM_DYN>>>(Ah, Bh, bias, ls, CoutF, outH, M, Nn, K, doGelu);
}

extern "C" void kernel_launch(void* const* d_in, const int* in_sizes, int n_in,
                              void* d_out, int out_size)
{
    (void)n_in; (void)out_size;
    const float *x, *ln1_g, *ln1_b, *qkv_w, *proj_w, *proj_b, *ls1_g, *ln2_g, *ln2_b,
        *fc1_w, *fc1_b, *fc2_w, *fc2_b, *ls2_g, *ad_down_w, *ad_down_b, *ad_up_w, *ad_up_b,
        *bn3d_g, *bn3d_b, *norm3_g, *norm3_b, *attn1_w, *attn1_b, *bn2d_g, *bn2d_b;
    const int *cluster, *fgi, *maskp;
    x = (const float*)d_in[0];
    const float** fps[25] = {&ln1_g,&ln1_b,&qkv_w,&proj_w,&proj_b,&ls1_g,&ln2_g,&ln2_b,
                             &fc1_w,&fc1_b,&fc2_w,&fc2_b,&ls2_g,&ad_down_w,&ad_down_b,
                             &ad_up_w,&ad_up_b,&bn3d_g,&bn3d_b,&norm3_g,&norm3_b,
                             &attn1_w,&attn1_b,&bn2d_g,&bn2d_b};
    if (in_sizes[1] == TG_) {
        cluster = (const int*)d_in[1];
        fgi     = (const int*)d_in[2];
        maskp   = (const int*)d_in[3];
        for (int i = 0; i < 25; i++) *fps[i] = (const float*)d_in[4 + i];
    } else {
        for (int i = 0; i < 25; i++) *fps[i] = (const float*)d_in[1 + i];
        cluster = (const int*)d_in[26];
        fgi     = (const int*)d_in[27];
        maskp   = (const int*)d_in[28];
    }
    float* xout = (float*)d_out;

    float *p_stats = symF(g_stats), *p_bns = symF(g_bns), *p_bnb = symF(g_bnb),
          *p_bcorr = symF(g_bcorr);
    int *p_cnt = symI(g_cnt), *p_off = symI(g_off), *p_fill = symI(g_fill), *p_list = symI(g_list);
    int *p_mcnt = symI(g_mcnt), *p_mrows = symI(g_mrows), *p_mpos = symI(g_mpos);
    __nv_bfloat16 *p_ah = symH(g_ah), *p_qh = symH(g_qh), *p_hh = symH(g_hh),
                  *p_wqkvT = symH(g_wqkvT), *p_wprojT = symH(g_wprojT),
                  *p_wfc1T = symH(g_wfc1T), *p_wfc2T = symH(g_wfc2T);
    __half *p_zh = symX(g_zh), *p_xpat = symX(g_xpat), *p_hlocC = symX(g_hlocC),
           *p_wattnT = symX(g_wattnT), *p_tv = symX(g_tv), *p_t3 = symX(g_t3);

    // one-time handles (host-side only; GPU work identical every call)
    static cudaStream_t s2 = nullptr;
    static cudaEvent_t ev0 = nullptr, evA = nullptr, evB = nullptr, evC = nullptr,
                       evD = nullptr, evE = nullptr;
    if (!s2) {
        cudaStreamCreateWithFlags(&s2, cudaStreamNonBlocking);
        cudaEventCreateWithFlags(&ev0, cudaEventDisableTiming);
        cudaEventCreateWithFlags(&evA, cudaEventDisableTiming);
        cudaEventCreateWithFlags(&evB, cudaEventDisableTiming);
        cudaEventCreateWithFlags(&evC, cudaEventDisableTiming);
        cudaEventCreateWithFlags(&evD, cudaEventDisableTiming);
        cudaEventCreateWithFlags(&evE, cudaEventDisableTiming);
        cudaFuncSetAttribute(tgemm_kernel, cudaFuncAttributeMaxDynamicSharedMemorySize, SMEM_DYN);
        cudaFuncSetAttribute(tgemm_views_kernel, cudaFuncAttributeMaxDynamicSharedMemorySize, SMEM_DYN);
        cudaFuncSetAttribute(fattn_kernel, cudaFuncAttributeMaxDynamicSharedMemorySize, ATT_SMEM);
    }

    // ---- fork side stream for setup (weights, memcpy, CSR)
    cudaEventRecord(ev0, 0);
    cudaStreamWaitEvent(s2, ev0, 0);

    dim3 tb(32, 8);
    transW_kernel<<<dim3(3 * C_ / 32, C_ / 32), tb, 0, s2>>>(qkv_w, p_wqkvT, C_, 3 * C_);
    transW_kernel<<<dim3(C_ / 32, C_ / 32), tb, 0, s2>>>(proj_w, p_wprojT, C_, C_);
    transW_kernel<<<dim3(4 * C_ / 32, C_ / 32), tb, 0, s2>>>(fc1_w, p_wfc1T, C_, 4 * C_);
    transW_kernel<<<dim3(C_ / 32, 4 * C_ / 32), tb, 0, s2>>>(fc2_w, p_wfc2T, 4 * C_, C_);
    cudaEventRecord(evA, s2);

    cudaMemcpyAsync(xout, x, sizeof(float) * (size_t)T_ * C_, cudaMemcpyDeviceToDevice, s2);
    cudaEventRecord(evC, s2);

    for (int v = 0; v < V_; v++)
        transWh_kernel<<<dim3(C_ / 32, C_ / 32), tb, 0, s2>>>(attn1_w + (size_t)v * C_ * C_,
                                                              norm3_g + v * C_,
                                                              p_wattnT + (size_t)v * C_ * C_, C_, C_);
    biascorr_kernel<<<dim3(C_ / 128, V_), 128, 0, s2>>>(attn1_w, norm3_b, attn1_b, p_bcorr);
    cudaMemsetAsync(p_cnt, 0, sizeof(int) * NSLOT_ * D2_, s2);
    cudaMemsetAsync(p_mcnt, 0, sizeof(int) * V_, s2);
    cudaMemsetAsync(p_mpos, 0xFF, sizeof(int) * V_ * TG_, s2);
    cudaMemsetAsync(p_stats, 0, sizeof(float) * NSLOT_ * 2 * C_, s2);
    hist_kernel<<<dim3(TG_ / 256, NSLOT_), 256, 0, s2>>>(fgi, cluster, p_cnt);
    scan_kernel<<<NSLOT_, 256, 0, s2>>>(p_cnt, p_off, p_fill);
    fillcsr_kernel<<<dim3(TG_ / 256, NSLOT_), 256, 0, s2>>>(fgi, cluster, p_fill, p_list);
    maskfill_kernel<<<dim3(TG_ / 256, V_), 256, 0, s2>>>(maskp, p_mcnt, p_mrows, p_mpos);
    cudaEventRecord(evB, s2);

    // ---- main chain
    ln_kernel<<<T_, 128>>>(x, ln1_g, ln1_b, p_ah);
    cudaStreamWaitEvent(0, evA, 0);
    tgemm(p_ah, p_wqkvT, nullptr, nullptr, nullptr, p_qh, T_, 3 * C_, C_, 0);
    fattn_kernel<<<dim3(9, H_, B_), 128, ATT_SMEM>>>(p_qh, p_ah);
    cudaStreamWaitEvent(0, evC, 0);
    tgemm(p_ah, p_wprojT, proj_b, ls1_g, xout, nullptr, T_, C_, C_, 0);

    ln_kernel<<<T_, 128>>>(xout, ln2_g, ln2_b, p_ah);
    tgemm(p_ah, p_wfc1T, fc1_b, nullptr, nullptr, p_hh, T_, 4 * C_, C_, 1);
    tgemm(p_hh, p_wfc2T, fc2_b, nullptr, nullptr, p_ah, T_, C_, 4 * C_, 0);
    // fused adapter + residual + unit-gamma LN -> fp16 z + fp16 xpat
    adapterln_kernel<<<T_, 128>>>(p_ah, ls2_g, ad_down_w, ad_down_b, ad_up_w, ad_up_b,
                                  xout, p_zh, p_xpat);
    cudaEventRecord(evD, 0);

    // ---- slot-6 (cluster) pooling on s2, overlapping the view GEMM
    cudaStreamWaitEvent(s2, evD, 0);
    gatherB_kernel<<<dim3((NC_ + 3) / 4, 1), 128, 0, s2>>>(p_xpat, p_hlocC, p_mpos, p_off, p_cnt,
                                                           p_list, p_tv, p_t3, 6);
    seg_statsB_kernel<<<dim3(64, 1), C_, 0, s2>>>(p_tv, p_t3, p_stats, 6);
    cudaEventRecord(evE, s2);

    cudaStreamWaitEvent(0, evB, 0);
    // all 6 view GEMMs in one launch (masked rows only, fp16 single pass, fp16 out)
    tgemm_views_kernel<<<dim3(3, TG_ / 128, V_), 256, SMEM_DYN>>>(p_zh, p_wattnT,
                                                                  p_bcorr, p_mcnt, p_mrows, p_hlocC);

    // view-slot pooling + stats on main
    gatherB_kernel<<<dim3((D2_ + 3) / 4, 6), 128>>>(p_xpat, p_hlocC, p_mpos, p_off, p_cnt,
                                                    p_list, p_tv, p_t3, 0);
    seg_statsB_kernel<<<dim3(64, 6), C_>>>(p_tv, p_t3, p_stats, 0);
    cudaStreamWaitEvent(0, evE, 0);
    bnparam_kernel<<<NSLOT_, C_>>>(p_stats, bn2d_g, bn2d_b, bn3d_g, bn3d_b, p_bns, p_bnb);

    // cosine-weighted fusion (BN+gelu applied on the fly, fp16 tables)
    sims_kernel<<<(TG_ * 32 + 255) / 256, 256>>>(xout, cluster, fgi, p_t3, p_tv, p_bns, p_bnb);
}

// round 16
// speedup vs baseline: 1.0055x; 1.0055x over previous
#include <cuda_runtime.h>
#include <cuda_bf16.h>
#include <cuda_fp16.h>
#include <cfloat>
#include <cmath>
#include <cstdint>

// ---------------------------------------------------------------------------
// Problem constants
// ---------------------------------------------------------------------------
constexpr int B_  = 32;
constexpr int N_  = 513;      // G+1 tokens
constexpr int C_  = 384;
constexpr int H_  = 6;
constexpr int G_  = 512;
constexpr int V_  = 6;
constexpr int NC_ = 2048;     // N_CLUSTERS
constexpr int D2_ = 6272;     // B*GRID*GRID
constexpr int T_  = B_ * N_;  // 16416 tokens
constexpr int TG_ = B_ * G_;  // 16384 patch tokens
constexpr int NSLOT_ = 7;     // 6 views + cluster
constexpr float EPS_ = 1e-5f;

// ---------------------------------------------------------------------------
// Scratch (static device globals; no runtime allocation)
// ---------------------------------------------------------------------------
__device__ __half g_tv   [V_ * D2_ * C_];  // pooled t per view (fp16)
__device__ __half g_t3   [NC_ * C_];       // pooled t for cluster path (fp16)
__device__ float g_stats[NSLOT_ * 2 * C_];
__device__ float g_bns  [NSLOT_ * C_];     // BN scale per slot
__device__ float g_bnb  [NSLOT_ * C_];     // BN shift per slot
__device__ float g_bcorr[V_ * C_];

// CSR for segment pooling (slot 0..5 = views over fgi, slot 6 = cluster)
__device__ int g_cnt [NSLOT_ * D2_];
__device__ int g_off [NSLOT_ * D2_];
__device__ int g_fill[NSLOT_ * D2_];
__device__ int g_list[NSLOT_ * TG_];
// mask compaction
__device__ int g_mcnt [V_];
__device__ int g_mrows[V_ * TG_];
__device__ int g_mpos [V_ * TG_];

// bf16/fp16 staging
__device__ __nv_bfloat16 g_ah[T_ * C_];            // LN out / attn out / fc2 out (bf16)
__device__ __half        g_zh[TG_ * C_];           // unit-gamma LN of patch rows (fp16)
__device__ __half        g_xpat[TG_ * C_];         // compact patch xout rows (fp16)
__device__ __half        g_hlocC[V_ * TG_ * C_];   // compacted per-view hloc (fp16)
__device__ __nv_bfloat16 g_qh[T_ * 3 * C_];        // qkv bf16
__device__ __nv_bfloat16 g_hh[T_ * 4 * C_];        // fc1 out bf16
__device__ __nv_bfloat16 g_wqkvT[3 * C_ * C_];
__device__ __nv_bfloat16 g_wprojT[C_ * C_];
__device__ __nv_bfloat16 g_wfc1T [4 * C_ * C_];
__device__ __nv_bfloat16 g_wfc2T [C_ * 4 * C_];
__device__ __half        g_wattnT[V_ * C_ * C_];   // fp16 view weights

// ---------------------------------------------------------------------------
// Portable PTX helpers (sm_80+ baseline)
// ---------------------------------------------------------------------------
__device__ __forceinline__ uint32_t smem_u32(const void* p) {
    uint32_t a;
    asm("{ .reg .u64 t; cvta.to.shared.u64 t, %1; cvt.u32.u64 %0, t; }" : "=r"(a) : "l"(p));
    return a;
}
__device__ __forceinline__ void cpa16(uint32_t dst, const void* src, int sz) {
    asm volatile("cp.async.cg.shared.global [%0], [%1], 16, %2;"
                 :: "r"(dst), "l"(src), "r"(sz) : "memory");
}
#define CPA_COMMIT() asm volatile("cp.async.commit_group;" ::: "memory")
#define CPA_WAIT1()  asm volatile("cp.async.wait_group 1;" ::: "memory")
#define CPA_WAIT0()  asm volatile("cp.async.wait_group 0;" ::: "memory")

__device__ __forceinline__ void ldm_x4(uint32_t* r, uint32_t addr) {
    asm volatile("ldmatrix.sync.aligned.m8n8.x4.shared.b16 {%0,%1,%2,%3}, [%4];"
                 : "=r"(r[0]), "=r"(r[1]), "=r"(r[2]), "=r"(r[3]) : "r"(addr));
}
__device__ __forceinline__ void ldm_x4_trans(uint32_t* r, uint32_t addr) {
    asm volatile("ldmatrix.sync.aligned.m8n8.x4.trans.shared.b16 {%0,%1,%2,%3}, [%4];"
                 : "=r"(r[0]), "=r"(r[1]), "=r"(r[2]), "=r"(r[3]) : "r"(addr));
}
__device__ __forceinline__ void mma_bf16(float* c, const uint32_t* a, uint32_t b0, uint32_t b1) {
    asm volatile("mma.sync.aligned.m16n8k16.row.col.f32.bf16.bf16.f32 "
                 "{%0,%1,%2,%3}, {%4,%5,%6,%7}, {%8,%9}, {%0,%1,%2,%3};"
                 : "+f"(c[0]), "+f"(c[1]), "+f"(c[2]), "+f"(c[3])
                 : "r"(a[0]), "r"(a[1]), "r"(a[2]), "r"(a[3]), "r"(b0), "r"(b1));
}
__device__ __forceinline__ void mma_f16(float* c, const uint32_t* a, uint32_t b0, uint32_t b1) {
    asm volatile("mma.sync.aligned.m16n8k16.row.col.f32.f16.f16.f32 "
                 "{%0,%1,%2,%3}, {%4,%5,%6,%7}, {%8,%9}, {%0,%1,%2,%3};"
                 : "+f"(c[0]), "+f"(c[1]), "+f"(c[2]), "+f"(c[3])
                 : "r"(a[0]), "r"(a[1]), "r"(a[2]), "r"(a[3]), "r"(b0), "r"(b1));
}
__device__ __forceinline__ uint32_t packbf(float lo, float hi) {
    uint32_t r;
    asm("cvt.rn.bf16x2.f32 %0, %1, %2;" : "=r"(r) : "f"(hi), "f"(lo));
    return r;
}
__device__ __forceinline__ uint32_t packhf(float lo, float hi) {
    uint32_t r;
    asm("cvt.rn.f16x2.f32 %0, %1, %2;" : "=r"(r) : "f"(hi), "f"(lo));
    return r;
}

// ---------------------------------------------------------------------------
// Math helpers
// ---------------------------------------------------------------------------
__device__ __forceinline__ float geluf(float x) {
    return 0.5f * x * (1.0f + erff(x * 0.70710678118654752f));
}
__device__ __forceinline__ float warpSum(float v) {
    #pragma unroll
    for (int o = 16; o > 0; o >>= 1) v += __shfl_xor_sync(0xffffffffu, v, o);
    return v;
}

// ---------------------------------------------------------------------------
// bf16 HMMA GEMM, 3-stage cp.async pipeline, single barrier per K-iter.
// ---------------------------------------------------------------------------
constexpr int BM = 128, BN = 128, BK = 32;
constexpr int LDA = BK + 8;
constexpr int STAGE_ELEMS = BM * LDA + BN * LDA;   // 10240 elems = 20480 B
constexpr int SMEM_DYN = 3 * STAGE_ELEMS * 2;      // 61440 B

__global__ __launch_bounds__(256, 2)
void tgemm_kernel(const __nv_bfloat16* __restrict__ Ah,
                  const __nv_bfloat16* __restrict__ Bh,
                  const float* __restrict__ bias, const float* __restrict__ ls,
                  float* __restrict__ CoutF, __nv_bfloat16* __restrict__ outH,
                  int M, int Nn, int K, int doGelu)
{
    extern __shared__ __nv_bfloat16 smext[];
    uint32_t sbase = smem_u32(smext);

    int tid = threadIdx.x, lane = tid & 31, wid = tid >> 5;
    int wm = wid & 1, wn = wid >> 1;
    int m0 = blockIdx.y * BM, n0 = blockIdx.x * BN;

    const int total = K >> 5;

    float c[4][4][4];
    #pragma unroll
    for (int mi = 0; mi < 4; mi++)
        #pragma unroll
        for (int ni = 0; ni < 4; ni++)
            #pragma unroll
            for (int e = 0; e < 4; e++) c[mi][ni][e] = 0.0f;

    auto loadTiles = [&](int it, int s) {
        int k0 = it * BK;
        uint32_t aOff = sbase + (uint32_t)(s * STAGE_ELEMS) * 2;
        uint32_t bOff = aOff + (uint32_t)(BM * LDA) * 2;
        #pragma unroll
        for (int r = 0; r < 2; r++) {
            int idx = tid + r * 256;
            int row = idx >> 2;
            int ch  = (idx & 3) * 8;
            int gr  = m0 + row;
            int grc = gr < M ? gr : 0;
            cpa16(aOff + (uint32_t)(row * LDA + ch) * 2,
                  Ah + (size_t)grc * K + k0 + ch, gr < M ? 16 : 0);
            cpa16(bOff + (uint32_t)(row * LDA + ch) * 2,
                  Bh + (size_t)(n0 + row) * K + k0 + ch, 16);
        }
    };

    loadTiles(0, 0);
    CPA_COMMIT();
    if (total > 1) { loadTiles(1, 1); CPA_COMMIT(); }

    for (int it = 0; it < total; it++) {
        if (it + 1 < total) { CPA_WAIT1(); } else { CPA_WAIT0(); }
        __syncthreads();
        if (it + 2 < total) { loadTiles(it + 2, (it + 2) % 3); CPA_COMMIT(); }

        int cur = it % 3;
        uint32_t aB = sbase + (uint32_t)(cur * STAGE_ELEMS) * 2;
        uint32_t bB = aB + (uint32_t)(BM * LDA) * 2;

        #pragma unroll
        for (int k16 = 0; k16 < 2; k16++) {
            uint32_t a[4][4];
            #pragma unroll
            for (int mi = 0; mi < 4; mi++) {
                uint32_t addr = aB + (uint32_t)((wm * 64 + mi * 16 + (lane & 15)) * LDA
                                                + k16 * 16 + (lane >> 4) * 8) * 2;
                ldm_x4(a[mi], addr);
            }
            uint32_t b[2][4];
            #pragma unroll
            for (int bt = 0; bt < 2; bt++) {
                uint32_t addr = bB + (uint32_t)((wn * 32 + bt * 16 + (lane & 7) + ((lane >> 4) * 8)) * LDA
                                                + k16 * 16 + ((lane >> 3) & 1) * 8) * 2;
                ldm_x4(b[bt], addr);
            }
            #pragma unroll
            for (int mi = 0; mi < 4; mi++)
                #pragma unroll
                for (int ni = 0; ni < 4; ni++) {
                    const uint32_t* bb = b[ni >> 1];
                    int off = (ni & 1) * 2;
                    mma_bf16(c[mi][ni], a[mi], bb[off], bb[off + 1]);
                }
        }
    }

    int group = lane >> 2, qid = lane & 3;
    #pragma unroll
    for (int mi = 0; mi < 4; mi++) {
        #pragma unroll
        for (int ni = 0; ni < 4; ni++) {
            int col = n0 + wn * 32 + ni * 8 + qid * 2;
            #pragma unroll
            for (int half = 0; half < 2; half++) {
                int row = m0 + wm * 64 + mi * 16 + group + half * 8;
                if (row < M) {
                    float v0 = c[mi][ni][half * 2 + 0];
                    float v1 = c[mi][ni][half * 2 + 1];
                    if (bias) { v0 += bias[col]; v1 += bias[col + 1]; }
                    if (doGelu) { v0 = geluf(v0); v1 = geluf(v1); }
                    if (outH) {
                        *(uint32_t*)(outH + (size_t)row * Nn + col) = packbf(v0, v1);
                    } else {
                        float* cp = CoutF + (size_t)row * Nn + col;
                        if (ls) { cp[0] += ls[col] * v0; cp[1] += ls[col + 1] * v1; }
                        else    { cp[0] = v0; cp[1] = v1; }
                    }
                }
            }
        }
    }
}

// ---------------------------------------------------------------------------
// Batched per-view GEMM, fp16 single-pass, masked-row compaction,
// 3-stage pipeline, fp16 output. grid (3, 128, V).
// ---------------------------------------------------------------------------
__global__ __launch_bounds__(256, 2)
void tgemm_views_kernel(const __half* __restrict__ Zh,
                        const __half* __restrict__ WAll,
                        const float* __restrict__ bcorr, const int* __restrict__ mcnt,
                        const int* __restrict__ mrows, __half* __restrict__ hlocC)
{
    int v = blockIdx.z;
    int M = mcnt[v];
    int m0 = blockIdx.y * BM;
    if (m0 >= M) return;
    int n0 = blockIdx.x * BN;

    const __half* Bw = WAll + (size_t)v * C_ * C_;
    const float* bias = bcorr + v * C_;
    const int* rlist = mrows + v * TG_;
    __half* Cout = hlocC + (size_t)v * TG_ * C_;
    const int K = C_;

    extern __shared__ __nv_bfloat16 smext[];
    uint32_t sbase = smem_u32(smext);

    int tid = threadIdx.x, lane = tid & 31, wid = tid >> 5;
    int wm = wid & 1, wn = wid >> 1;

    const int total = K >> 5;            // 12

    float c[4][4][4];
    #pragma unroll
    for (int mi = 0; mi < 4; mi++)
        #pragma unroll
        for (int ni = 0; ni < 4; ni++)
            #pragma unroll
            for (int e = 0; e < 4; e++) c[mi][ni][e] = 0.0f;

    auto loadTiles = [&](int it, int s) {
        int k0 = it * BK;
        uint32_t aOff = sbase + (uint32_t)(s * STAGE_ELEMS) * 2;
        uint32_t bOff = aOff + (uint32_t)(BM * LDA) * 2;
        #pragma unroll
        for (int r = 0; r < 2; r++) {
            int idx = tid + r * 256;
            int row = idx >> 2;
            int ch  = (idx & 3) * 8;
            int rr  = m0 + row;
            int gr  = rr < M ? rlist[rr] : 0;
            cpa16(aOff + (uint32_t)(row * LDA + ch) * 2,
                  Zh + (size_t)gr * K + k0 + ch, rr < M ? 16 : 0);
            cpa16(bOff + (uint32_t)(row * LDA + ch) * 2,
                  Bw + (size_t)(n0 + row) * K + k0 + ch, 16);
        }
    };

    loadTiles(0, 0);
    CPA_COMMIT();
    loadTiles(1, 1);
    CPA_COMMIT();

    for (int it = 0; it < total; it++) {
        if (it + 1 < total) { CPA_WAIT1(); } else { CPA_WAIT0(); }
        __syncthreads();
        if (it + 2 < total) { loadTiles(it + 2, (it + 2) % 3); CPA_COMMIT(); }

        int cur = it % 3;
        uint32_t aB = sbase + (uint32_t)(cur * STAGE_ELEMS) * 2;
        uint32_t bB = aB + (uint32_t)(BM * LDA) * 2;

        #pragma unroll
        for (int k16 = 0; k16 < 2; k16++) {
            uint32_t a[4][4];
            #pragma unroll
            for (int mi = 0; mi < 4; mi++) {
                uint32_t addr = aB + (uint32_t)((wm * 64 + mi * 16 + (lane & 15)) * LDA
                                                + k16 * 16 + (lane >> 4) * 8) * 2;
                ldm_x4(a[mi], addr);
            }
            uint32_t b[2][4];
            #pragma unroll
            for (int bt = 0; bt < 2; bt++) {
                uint32_t addr = bB + (uint32_t)((wn * 32 + bt * 16 + (lane & 7) + ((lane >> 4) * 8)) * LDA
                                                + k16 * 16 + ((lane >> 3) & 1) * 8) * 2;
                ldm_x4(b[bt], addr);
            }
            #pragma unroll
            for (int mi = 0; mi < 4; mi++)
                #pragma unroll
                for (int ni = 0; ni < 4; ni++) {
                    const uint32_t* bb = b[ni >> 1];
                    int off = (ni & 1) * 2;
                    mma_f16(c[mi][ni], a[mi], bb[off], bb[off + 1]);
                }
        }
    }

    int group = lane >> 2, qid = lane & 3;
    #pragma unroll
    for (int mi = 0; mi < 4; mi++) {
        #pragma unroll
        for (int ni = 0; ni < 4; ni++) {
            int col = n0 + wn * 32 + ni * 8 + qid * 2;
            #pragma unroll
            for (int half = 0; half < 2; half++) {
                int row = m0 + wm * 64 + mi * 16 + group + half * 8;
                if (row < M) {
                    float v0 = c[mi][ni][half * 2 + 0] + bias[col];
                    float v1 = c[mi][ni][half * 2 + 1] + bias[col + 1];
                    *(uint32_t*)(Cout + (size_t)row * C_ + col) = packhf(v0, v1);
                }
            }
        }
    }
}

// ---------------------------------------------------------------------------
// Flash attention, bf16 HMMA (validated best config: 64q/128thr, static smem).
// ---------------------------------------------------------------------------
constexpr int LDQK = 72;

__global__ __launch_bounds__(128)
void fattn_kernel(const __nv_bfloat16* __restrict__ qkv, __nv_bfloat16* __restrict__ outH)
{
    __shared__ __nv_bfloat16 sQ[64 * LDQK], sK[64 * LDQK], sV[64 * LDQK];
    int tid = threadIdx.x, lane = tid & 31, wid = tid >> 5;
    int qt = blockIdx.x, h = blockIdx.y, b = blockIdx.z;
    size_t base = (size_t)b * N_ * 1152;

    #pragma unroll
    for (int it = 0; it < 4; it++) {
        int idx = tid + it * 128;
        int row = idx >> 3, seg = idx & 7;
        int qi = qt * 64 + row; if (qi > N_ - 1) qi = N_ - 1;
        *(uint4*)&sQ[row * LDQK + seg * 8] =
            *(const uint4*)(qkv + base + (size_t)qi * 1152 + h * 64 + seg * 8);
    }
    __syncthreads();

    uint32_t sqb = smem_u32(sQ), skb = smem_u32(sK), svb = smem_u32(sV);
    uint32_t aQ[4][4];
    #pragma unroll
    for (int k16 = 0; k16 < 4; k16++) {
        uint32_t addr = sqb + (uint32_t)((wid * 16 + (lane & 15)) * LDQK
                                         + k16 * 16 + (lane >> 4) * 8) * 2;
        ldm_x4(aQ[k16], addr);
    }

    float o[8][4];
    #pragma unroll
    for (int ch = 0; ch < 8; ch++)
        #pragma unroll
        for (int e = 0; e < 4; e++) o[ch][e] = 0.0f;
    float m0 = -1e30f, m1 = -1e30f, l0 = 0.0f, l1 = 0.0f;
    int q2 = (lane & 3) * 2;

    for (int kt = 0; kt < 9; kt++) {
        __syncthreads();
        #pragma unroll
        for (int it = 0; it < 4; it++) {
            int idx = tid + it * 128;
            int row = idx >> 3, seg = idx & 7;
            int kv = kt * 64 + row; if (kv > N_ - 1) kv = N_ - 1;
            const __nv_bfloat16* src = qkv + base + (size_t)kv * 1152 + 384 + h * 64 + seg * 8;
            *(uint4*)&sK[row * LDQK + seg * 8] = *(const uint4*)src;
            *(uint4*)&sV[row * LDQK + seg * 8] = *(const uint4*)(src + 384);
        }
        __syncthreads();

        float s[8][4];
        #pragma unroll
        for (int ch = 0; ch < 8; ch++)
            #pragma unroll
            for (int e = 0; e < 4; e++) s[ch][e] = 0.0f;
        #pragma unroll
        for (int ng = 0; ng < 4; ng++) {
            #pragma unroll
            for (int k16 = 0; k16 < 4; k16++) {
                uint32_t bk[4];
                uint32_t addr = skb + (uint32_t)((ng * 16 + (lane & 7) + ((lane >> 4) * 8)) * LDQK
                                                 + k16 * 16 + ((lane >> 3) & 1) * 8) * 2;
                ldm_x4(bk, addr);
                mma_bf16(s[2 * ng],     aQ[k16], bk[0], bk[1]);
                mma_bf16(s[2 * ng + 1], aQ[k16], bk[2], bk[3]);
            }
        }

        float lm0 = -1e30f, lm1 = -1e30f;
        #pragma unroll
        for (int ch = 0; ch < 8; ch++) {
            int j = kt * 64 + ch * 8 + q2;
            #pragma unroll
            for (int e = 0; e < 4; e++) s[ch][e] *= 0.125f;
            if (j >= N_)     { s[ch][0] = -1e30f; s[ch][2] = -1e30f; }
            if (j + 1 >= N_) { s[ch][1] = -1e30f; s[ch][3] = -1e30f; }
            lm0 = fmaxf(lm0, fmaxf(s[ch][0], s[ch][1]));
            lm1 = fmaxf(lm1, fmaxf(s[ch][2], s[ch][3]));
        }
        lm0 = fmaxf(lm0, __shfl_xor_sync(0xffffffffu, lm0, 1));
        lm0 = fmaxf(lm0, __shfl_xor_sync(0xffffffffu, lm0, 2));
        lm1 = fmaxf(lm1, __shfl_xor_sync(0xffffffffu, lm1, 1));
        lm1 = fmaxf(lm1, __shfl_xor_sync(0xffffffffu, lm1, 2));
        float mn0 = fmaxf(m0, lm0), mn1 = fmaxf(m1, lm1);
        float c0f = __expf(m0 - mn0), c1f = __expf(m1 - mn1);
        l0 *= c0f; l1 *= c1f;
        #pragma unroll
        for (int ch = 0; ch < 8; ch++) {
            o[ch][0] *= c0f; o[ch][1] *= c0f; o[ch][2] *= c1f; o[ch][3] *= c1f;
        }
        uint32_t P[8][2];
        float ls0 = 0.0f, ls1 = 0.0f;
        #pragma unroll
        for (int ch = 0; ch < 8; ch++) {
            float p0 = __expf(s[ch][0] - mn0), p1 = __expf(s[ch][1] - mn0);
            float p2 = __expf(s[ch][2] - mn1), p3 = __expf(s[ch][3] - mn1);
            ls0 += p0 + p1; ls1 += p2 + p3;
            P[ch][0] = packbf(p0, p1);
            P[ch][1] = packbf(p2, p3);
        }
        ls0 += __shfl_xor_sync(0xffffffffu, ls0, 1);
        ls0 += __shfl_xor_sync(0xffffffffu, ls0, 2);
        ls1 += __shfl_xor_sync(0xffffffffu, ls1, 1);
        ls1 += __shfl_xor_sync(0xffffffffu, ls1, 2);
        l0 += ls0; l1 += ls1; m0 = mn0; m1 = mn1;

        #pragma unroll
        for (int dg = 0; dg < 4; dg++) {
            #pragma unroll
            for (int k16 = 0; k16 < 4; k16++) {
                uint32_t bv[4];
                uint32_t addr = svb + (uint32_t)((k16 * 16 + (lane & 15)) * LDQK
                                                 + dg * 16 + (lane >> 4) * 8) * 2;
                ldm_x4_trans(bv, addr);
                uint32_t ap[4] = {P[2 * k16][0], P[2 * k16][1],
                                  P[2 * k16 + 1][0], P[2 * k16 + 1][1]};
                mma_bf16(o[2 * dg],     ap, bv[0], bv[1]);
                mma_bf16(o[2 * dg + 1], ap, bv[2], bv[3]);
            }
        }
    }

    float i0 = 1.0f / l0, i1 = 1.0f / l1;
    int g = lane >> 2;
    int r0 = qt * 64 + wid * 16 + g, r1 = r0 + 8;
    #pragma unroll
    for (int ch = 0; ch < 8; ch++) {
        int col = h * 64 + ch * 8 + q2;
        if (r0 < N_)
            *(uint32_t*)(outH + (size_t)(b * N_ + r0) * C_ + col) = packbf(o[ch][0] * i0, o[ch][1] * i0);
        if (r1 < N_)
            *(uint32_t*)(outH + (size_t)(b * N_ + r1) * C_ + col) = packbf(o[ch][2] * i1, o[ch][3] * i1);
    }
}

// ---------------------------------------------------------------------------
// Weight transpose: bf16 (main GEMMs) and fp16 w/ row scale (views)
// ---------------------------------------------------------------------------
__global__ void transW_kernel(const float* __restrict__ W,
                              __nv_bfloat16* __restrict__ hiT, int K, int N)
{
    __shared__ float t[32][33];
    int n0 = blockIdx.x * 32, k0 = blockIdx.y * 32;
    int tx = threadIdx.x, ty = threadIdx.y;
    #pragma unroll
    for (int r = 0; r < 4; r++)
        t[ty + 8 * r][tx] = W[(size_t)(k0 + ty + 8 * r) * N + n0 + tx];
    __syncthreads();
    #pragma unroll
    for (int r = 0; r < 4; r++) {
        int nl = ty + 8 * r;
        hiT[(size_t)(n0 + nl) * K + k0 + tx] = __float2bfloat16(t[tx][nl]);
    }
}

__global__ void transWh_kernel(const float* __restrict__ W, const float* __restrict__ g,
                               __half* __restrict__ outT, int K, int N)
{
    __shared__ float t[32][33];
    int n0 = blockIdx.x * 32, k0 = blockIdx.y * 32;
    int tx = threadIdx.x, ty = threadIdx.y;
    #pragma unroll
    for (int r = 0; r < 4; r++)
        t[ty + 8 * r][tx] = W[(size_t)(k0 + ty + 8 * r) * N + n0 + tx];
    __syncthreads();
    float gs = g[k0 + tx];
    #pragma unroll
    for (int r = 0; r < 4; r++) {
        int nl = ty + 8 * r;
        outT[(size_t)(n0 + nl) * K + k0 + tx] = __float2half_rn(t[tx][nl] * gs);
    }
}

// ---------------------------------------------------------------------------
__global__ void biascorr_kernel(const float* __restrict__ attnW, const float* __restrict__ nb,
                                const float* __restrict__ ab, float* __restrict__ bc)
{
    int v = blockIdx.y;
    int n = blockIdx.x * 128 + threadIdx.x;
    const float* W = attnW + (size_t)v * C_ * C_;
    const float* b = nb + v * C_;
    float s = 0.0f;
    for (int k = 0; k < C_; k++) s += b[k] * W[(size_t)k * C_ + n];
    bc[v * C_ + n] = ab[v * C_ + n] + s;
}

// ---------------------------------------------------------------------------
// CSR build + mask compaction
// ---------------------------------------------------------------------------
__global__ void hist_kernel(const int* __restrict__ fgi, const int* __restrict__ cluster,
                            int* __restrict__ cnt)
{
    int v = blockIdx.y;
    int r = blockIdx.x * 256 + threadIdx.x;
    if (r >= TG_) return;
    int idx = (v < 6) ? fgi[v * TG_ + r] : cluster[r];
    atomicAdd(&cnt[v * D2_ + idx], 1);
}

__global__ void scan_kernel(const int* __restrict__ cnt, int* __restrict__ off,
                            int* __restrict__ fill)
{
    int v = blockIdx.x;
    int R = (v == 6) ? NC_ : D2_;
    const int* c = cnt + v * D2_;
    int* o = off + v * D2_;
    int* f = fill + v * D2_;
    __shared__ int part[256];
    int tid = threadIdx.x;
    int per = (R + 255) / 256;
    int base = tid * per;
    int s = 0;
    for (int i = 0; i < per; i++) { int j = base + i; if (j < R) s += c[j]; }
    part[tid] = s;
    __syncthreads();
    if (tid == 0) {
        int acc = 0;
        for (int i = 0; i < 256; i++) { int t = part[i]; part[i] = acc; acc += t; }
    }
    __syncthreads();
    int acc = part[tid];
    for (int i = 0; i < per; i++) {
        int j = base + i;
        if (j < R) { o[j] = acc; f[j] = acc; acc += c[j]; }
    }
}

__global__ void fillcsr_kernel(const int* __restrict__ fgi, const int* __restrict__ cluster,
                               int* __restrict__ fill, int* __restrict__ list)
{
    int v = blockIdx.y;
    int r = blockIdx.x * 256 + threadIdx.x;
    if (r >= TG_) return;
    int idx = (v < 6) ? fgi[v * TG_ + r] : cluster[r];
    int p = atomicAdd(&fill[v * D2_ + idx], 1);
    list[v * TG_ + p] = r;
}

__global__ void maskfill_kernel(const int* __restrict__ maskp, int* __restrict__ mcnt,
                                int* __restrict__ mrows, int* __restrict__ mpos)
{
    int v = blockIdx.y;
    int r = blockIdx.x * 256 + threadIdx.x;
    if (r >= TG_) return;
    if (maskp[v * TG_ + r]) {
        int p = atomicAdd(&mcnt[v], 1);
        mrows[v * TG_ + p] = r;
        mpos[v * TG_ + r] = p;
    }
}

// ---------------------------------------------------------------------------
// Batched gather-pool: warp per segment, 4 segments per block, fp16 in/out.
// slotBase selects slot range: slot = blockIdx.y + slotBase.
// ---------------------------------------------------------------------------
__global__ __launch_bounds__(128)
void gatherB_kernel(const __half* __restrict__ xpat, const __half* __restrict__ hlocC,
                    const int* __restrict__ mpos,
                    const int* __restrict__ off, const int* __restrict__ cnt,
                    const int* __restrict__ list,
                    __half* __restrict__ tv, __half* __restrict__ t3, int slotBase)
{
    int slot = blockIdx.y + slotBase;
    int warp = threadIdx.x >> 5, lane = threadIdx.x & 31;
    int j = blockIdx.x * 4 + warp;
    int R = (slot == 6) ? NC_ : D2_;
    if (j >= R) return;
    int base = off[slot * D2_ + j];
    int k = cnt[slot * D2_ + j];
    const int* rows = list + slot * TG_ + base;
    const __half2* xp2 = (const __half2*)xpat;
    const __half2* hC2 = (const __half2*)(hlocC + (size_t)slot * TG_ * C_);
    const int* mp = mpos + slot * TG_;

    float mxx[6], mxy[6], sx[6], sy[6];
    #pragma unroll
    for (int kk = 0; kk < 6; kk++) { mxx[kk] = -FLT_MAX; mxy[kk] = -FLT_MAX; sx[kk] = 0.0f; sy[kk] = 0.0f; }

    for (int i = 0; i < k; i++) {
        int r = rows[i];
        const __half2* src = xp2 + (size_t)r * 192;
        int p = (slot < 6) ? mp[r] : -1;
        if (p >= 0) {
            const __half2* hp = hC2 + (size_t)p * 192;
            #pragma unroll
            for (int kk = 0; kk < 6; kk++) {
                float2 v = __half22float2(src[lane + 32 * kk]);
                float2 h = __half22float2(hp[lane + 32 * kk]);
                v.x += h.x; v.y += h.y;
                mxx[kk] = fmaxf(mxx[kk], v.x); mxy[kk] = fmaxf(mxy[kk], v.y);
                sx[kk] += v.x; sy[kk] += v.y;
            }
        } else {
            #pragma unroll
            for (int kk = 0; kk < 6; kk++) {
                float2 v = __half22float2(src[lane + 32 * kk]);
                mxx[kk] = fmaxf(mxx[kk], v.x); mxy[kk] = fmaxf(mxy[kk], v.y);
                sx[kk] += v.x; sy[kk] += v.y;
            }
        }
    }

    __half* tp = (slot == 6) ? (t3 + (size_t)j * C_)
                             : (tv + ((size_t)slot * D2_ + j) * C_);
    if (k > 0) {
        float inv = 1.0f / (float)k;
        #pragma unroll
        for (int kk = 0; kk < 6; kk++) {
            *(uint32_t*)(tp + 2 * (lane + 32 * kk)) =
                packhf(mxx[kk] + sx[kk] * inv, mxy[kk] + sy[kk] * inv);
        }
    } else {
        #pragma unroll
        for (int kk = 0; kk < 6; kk++)
            *(uint32_t*)(tp + 2 * (lane + 32 * kk)) = 0u;
    }
}

// ---------------------------------------------------------------------------
__global__ void seg_statsB_kernel(const __half* __restrict__ tv, const __half* __restrict__ t3,
                                  float* __restrict__ stat, int slotBase)
{
    int slot = blockIdx.y + slotBase;
    int R = (slot == 6) ? NC_ : D2_;
    const __half* t = (slot == 6) ? t3 : tv + (size_t)slot * D2_ * C_;
    float* st = stat + slot * 2 * C_;
    int c = threadIdx.x;  // 384
    int rows_per = (R + gridDim.x - 1) / gridDim.x;
    int r0 = blockIdx.x * rows_per;
    int r1 = r0 + rows_per; if (r1 > R) r1 = R;
    float s1 = 0.0f, s2 = 0.0f;
    for (int r = r0; r < r1; r++) {
        float v = __half2float(t[(size_t)r * C_ + c]);
        s1 += v; s2 += v * v;
    }
    atomicAdd(&st[c], s1);
    atomicAdd(&st[C_ + c], s2);
}

// ---------------------------------------------------------------------------
__global__ void bnparam_kernel(const float* __restrict__ stat,
                               const float* __restrict__ bn2d_g, const float* __restrict__ bn2d_b,
                               const float* __restrict__ bn3d_g, const float* __restrict__ bn3d_b,
                               float* __restrict__ bns, float* __restrict__ bnb)
{
    int slot = blockIdx.x;
    int c = threadIdx.x;
    int R = (slot == 6) ? NC_ : D2_;
    const float* st = stat + slot * 2 * C_;
    float mean = st[c] / (float)R;
    float var  = fmaxf(st[C_ + c] / (float)R - mean * mean, 0.0f);
    float g = (slot == 6) ? bn3d_g[c] : bn2d_g[slot * C_ + c];
    float b = (slot == 6) ? bn3d_b[c] : bn2d_b[slot * C_ + c];
    float sc = g * rsqrtf(var + EPS_);
    bns[slot * C_ + c] = sc;
    bnb[slot * C_ + c] = b - mean * sc;
}

// ---------------------------------------------------------------------------
// LayerNorm over C -> bf16
// ---------------------------------------------------------------------------
__global__ void ln_kernel(const float* __restrict__ in,
                          const float* __restrict__ gam,
                          const float* __restrict__ bet,
                          __nv_bfloat16* __restrict__ outHi)
{
    int r = blockIdx.x;
    int tid = threadIdx.x;   // 128
    const float* row = in + (size_t)r * C_;
    float v0 = row[tid], v1 = row[tid + 128], v2 = row[tid + 256];
    __shared__ float sh[256];
    sh[tid] = v0 + v1 + v2;
    sh[128 + tid] = v0 * v0 + v1 * v1 + v2 * v2;
    __syncthreads();
    #pragma unroll
    for (int o = 64; o > 0; o >>= 1) {
        if (tid < o) { sh[tid] += sh[tid + o]; sh[128 + tid] += sh[128 + tid + o]; }
        __syncthreads();
    }
    float mean = sh[0] / C_;
    float var  = fmaxf(sh[128] / C_ - mean * mean, 0.0f);
    float inv  = rsqrtf(var + EPS_);
    #pragma unroll
    for (int k = 0; k < 3; k++) {
        int c = tid + 128 * k;
        float vv = (k == 0) ? v0 : (k == 1) ? v1 : v2;
        float y = (vv - mean) * inv;
        y = y * gam[c] + bet[c];
        outHi[(size_t)r * C_ + c] = __float2bfloat16(y);
    }
}

// ---------------------------------------------------------------------------
// Fused adapter + residual + unit-gamma LN -> fp16 z + fp16 compact xpat.
// ---------------------------------------------------------------------------
__global__ void adapterln_kernel(const __nv_bfloat16* __restrict__ fc2out,
                                 const float* __restrict__ ls2,
                                 const float* __restrict__ dw, const float* __restrict__ db,
                                 const float* __restrict__ uw, const float* __restrict__ ub,
                                 float* __restrict__ xout, __half* __restrict__ zh,
                                 __half* __restrict__ xpat)
{
    int t = blockIdx.x;
    int tid = threadIdx.x;  // 128
    __shared__ float xf[C_];
    __shared__ float h16[16];
    __shared__ float sh[256];
    #pragma unroll
    for (int k = 0; k < 3; k++) {
        int c = tid + 128 * k;
        xf[c] = ls2[c] * __bfloat162float(fc2out[(size_t)t * C_ + c]);
    }
    __syncthreads();
    int wid = tid >> 5, lane = tid & 31;
    #pragma unroll
    for (int jj = 0; jj < 4; jj++) {
        int j = wid * 4 + jj;
        float p = 0.0f;
        #pragma unroll
        for (int k = 0; k < 12; k++) {
            int c = lane + 32 * k;
            p += xf[c] * dw[c * 16 + j];
        }
        p = warpSum(p);
        if (lane == 0) h16[j] = geluf(p + db[j]);
    }
    __syncthreads();
    float nv[3];
    float s1 = 0.0f, s2 = 0.0f;
    #pragma unroll
    for (int k = 0; k < 3; k++) {
        int c = tid + 128 * k;
        float a = ub[c];
        #pragma unroll
        for (int j = 0; j < 16; j++) a += h16[j] * uw[j * C_ + c];
        float v = xout[(size_t)t * C_ + c] + xf[c] + 0.5f * a;
        xout[(size_t)t * C_ + c] = v;
        nv[k] = v;
        s1 += v; s2 += v * v;
    }
    sh[tid] = s1; sh[128 + tid] = s2;
    __syncthreads();
    #pragma unroll
    for (int o = 64; o > 0; o >>= 1) {
        if (tid < o) { sh[tid] += sh[tid + o]; sh[128 + tid] += sh[128 + tid + o]; }
        __syncthreads();
    }
    int bb = t / N_, idx = t - bb * N_;
    if (idx == 0) return;               // CLS token: no z/xpat
    float mean = sh[0] / C_;
    float var  = fmaxf(sh[128] / C_ - mean * mean, 0.0f);
    float inv  = rsqrtf(var + EPS_);
    size_t zr = (size_t)(bb * G_ + idx - 1) * C_;
    #pragma unroll
    for (int k = 0; k < 3; k++) {
        int c = tid + 128 * k;
        zh[zr + c]   = __float2half_rn((nv[k] - mean) * inv);
        xpat[zr + c] = __float2half_rn(nv[k]);
    }
}

// ---------------------------------------------------------------------------
// Final fusion: BN+gelu applied on the fly from fp16 pooled tables.
// ---------------------------------------------------------------------------
__global__ void sims_kernel(float* __restrict__ xout, const int* __restrict__ cluster,
                            const int* __restrict__ fgi,
                            const __half* __restrict__ t3, const __half* __restrict__ tv,
                            const float* __restrict__ bns, const float* __restrict__ bnb)
{
    int gw = (blockIdx.x * blockDim.x + threadIdx.x) >> 5;
    int lane = threadIdx.x & 31;
    if (gw >= TG_) return;
    int r = gw;
    int bb = r >> 9, gg = r & 511;
    size_t tok = (size_t)(bb * N_ + 1 + gg) * C_;

    float xr[12];
    const __half* xp = t3 + (size_t)cluster[r] * C_;
    float nx = 0.0f;
    #pragma unroll
    for (int k = 0; k < 12; k++) {
        int c = lane + 32 * k;
        float y = geluf(__half2float(xp[c]) * bns[6 * C_ + c] + bnb[6 * C_ + c]);
        xr[k] = y; nx += y * y;
    }
    nx = warpSum(nx);
    float nrmx = fmaxf(sqrtf(nx), 1e-8f);

    float d2[6][12];
    float w[6];
    float wsum = 0.0f;
    #pragma unroll
    for (int v = 0; v < 6; v++) {
        int ij = fgi[v * TG_ + r];
        const __half* dp = tv + ((size_t)v * D2_ + ij) * C_;
        float dot = 0.0f, nd = 0.0f;
        #pragma unroll
        for (int k = 0; k < 12; k++) {
            int c = lane + 32 * k;
            float dv = geluf(__half2float(dp[c]) * bns[v * C_ + c] + bnb[v * C_ + c]);
            d2[v][k] = dv;
            dot += dv * xr[k];
            nd  += dv * dv;
        }
        dot = warpSum(dot);
        nd  = warpSum(nd);
        float cosv = dot / (fmaxf(sqrtf(nd), 1e-8f) * nrmx);
        w[v] = (cosv + 1.0f) * 0.5f;
        wsum += w[v];
    }
    float inv = 1.0f / wsum;
    #pragma unroll
    for (int k = 0; k < 12; k++) {
        float a = 0.0f;
        #pragma unroll
        for (int v = 0; v < 6; v++) a += w[v] * d2[v][k];
        xout[tok + lane + 32 * k] += a * inv;   // COEF_PRO = 1
    }
}

// ---------------------------------------------------------------------------
// Host launcher
// ---------------------------------------------------------------------------
static float* symF(const void* sym) { void* p = nullptr; cudaGetSymbolAddress(&p, sym); return (float*)p; }
static int*   symI(const void* sym) { void* p = nullptr; cudaGetSymbolAddress(&p, sym); return (int*)p; }
static __nv_bfloat16* symH(const void* sym) { void* p = nullptr; cudaGetSymbolAddress(&p, sym); return (__nv_bfloat16*)p; }
static __half* symX(const void* sym) { void* p = nullptr; cudaGetSymbolAddress(&p, sym); return (__half*)p; }

static void tgemm(const __nv_bfloat16* Ah, const __nv_bfloat16* Bh,
                  const float* bias, const float* ls, float* CoutF, __nv_bfloat16* outH,
                  int M, int Nn, int K, int doGelu)
{
    dim3 grid(Nn / 128, (M + 127) / 128);
    tgemm_kernel<<<grid, 256, SMEM_DYN>>>(Ah, Bh, bias, ls, CoutF, outH, M, Nn, K, doGelu);
}

extern "C" void kernel_launch(void* const* d_in, const int* in_sizes, int n_in,
                              void* d_out, int out_size)
{
    (void)n_in; (void)out_size;
    const float *x, *ln1_g, *ln1_b, *qkv_w, *proj_w, *proj_b, *ls1_g, *ln2_g, *ln2_b,
        *fc1_w, *fc1_b, *fc2_w, *fc2_b, *ls2_g, *ad_down_w, *ad_down_b, *ad_up_w, *ad_up_b,
        *bn3d_g, *bn3d_b, *norm3_g, *norm3_b, *attn1_w, *attn1_b, *bn2d_g, *bn2d_b;
    const int *cluster, *fgi, *maskp;
    x = (const float*)d_in[0];
    const float** fps[25] = {&ln1_g,&ln1_b,&qkv_w,&proj_w,&proj_b,&ls1_g,&ln2_g,&ln2_b,
                             &fc1_w,&fc1_b,&fc2_w,&fc2_b,&ls2_g,&ad_down_w,&ad_down_b,
                             &ad_up_w,&ad_up_b,&bn3d_g,&bn3d_b,&norm3_g,&norm3_b,
                             &attn1_w,&attn1_b,&bn2d_g,&bn2d_b};
    if (in_sizes[1] == TG_) {
        cluster = (const int*)d_in[1];
        fgi     = (const int*)d_in[2];
        maskp   = (const int*)d_in[3];
        for (int i = 0; i < 25; i++) *fps[i] = (const float*)d_in[4 + i];
    } else {
        for (int i = 0; i < 25; i++) *fps[i] = (const float*)d_in[1 + i];
        cluster = (const int*)d_in[26];
        fgi     = (const int*)d_in[27];
        maskp   = (const int*)d_in[28];
    }
    float* xout = (float*)d_out;

    float *p_stats = symF(g_stats), *p_bns = symF(g_bns), *p_bnb = symF(g_bnb),
          *p_bcorr = symF(g_bcorr);
    int *p_cnt = symI(g_cnt), *p_off = symI(g_off), *p_fill = symI(g_fill), *p_list = symI(g_list);
    int *p_mcnt = symI(g_mcnt), *p_mrows = symI(g_mrows), *p_mpos = symI(g_mpos);
    __nv_bfloat16 *p_ah = symH(g_ah), *p_qh = symH(g_qh), *p_hh = symH(g_hh),
                  *p_wqkvT = symH(g_wqkvT), *p_wprojT = symH(g_wprojT),
                  *p_wfc1T = symH(g_wfc1T), *p_wfc2T = symH(g_wfc2T);
    __half *p_zh = symX(g_zh), *p_xpat = symX(g_xpat), *p_hlocC = symX(g_hlocC),
           *p_wattnT = symX(g_wattnT), *p_tv = symX(g_tv), *p_t3 = symX(g_t3);

    // one-time handles (host-side only; GPU work identical every call)
    static cudaStream_t s2 = nullptr;
    static cudaEvent_t ev0 = nullptr, evA = nullptr, evB = nullptr, evC = nullptr,
                       evD = nullptr, evE = nullptr;
    if (!s2) {
        cudaStreamCreateWithFlags(&s2, cudaStreamNonBlocking);
        cudaEventCreateWithFlags(&ev0, cudaEventDisableTiming);
        cudaEventCreateWithFlags(&evA, cudaEventDisableTiming);
        cudaEventCreateWithFlags(&evB, cudaEventDisableTiming);
        cudaEventCreateWithFlags(&evC, cudaEventDisableTiming);
        cudaEventCreateWithFlags(&evD, cudaEventDisableTiming);
        cudaEventCreateWithFlags(&evE, cudaEventDisableTiming);
        cudaFuncSetAttribute(tgemm_kernel, cudaFuncAttributeMaxDynamicSharedMemorySize, SMEM_DYN);
        cudaFuncSetAttribute(tgemm_views_kernel, cudaFuncAttributeMaxDynamicSharedMemorySize, SMEM_DYN);
    }

    // ---- fork side stream for setup (weights, memcpy, CSR)
    cudaEventRecord(ev0, 0);
    cudaStreamWaitEvent(s2, ev0, 0);

    dim3 tb(32, 8);
    transW_kernel<<<dim3(3 * C_ / 32, C_ / 32), tb, 0, s2>>>(qkv_w, p_wqkvT, C_, 3 * C_);
    transW_kernel<<<dim3(C_ / 32, C_ / 32), tb, 0, s2>>>(proj_w, p_wprojT, C_, C_);
    transW_kernel<<<dim3(4 * C_ / 32, C_ / 32), tb, 0, s2>>>(fc1_w, p_wfc1T, C_, 4 * C_);
    transW_kernel<<<dim3(C_ / 32, 4 * C_ / 32), tb, 0, s2>>>(fc2_w, p_wfc2T, 4 * C_, C_);
    cudaEventRecord(evA, s2);

    cudaMemcpyAsync(xout, x, sizeof(float) * (size_t)T_ * C_, cudaMemcpyDeviceToDevice, s2);
    cudaEventRecord(evC, s2);

    for (int v = 0; v < V_; v++)
        transWh_kernel<<<dim3(C_ / 32, C_ / 32), tb, 0, s2>>>(attn1_w + (size_t)v * C_ * C_,
                                                              norm3_g + v * C_,
                                                              p_wattnT + (size_t)v * C_ * C_, C_, C_);
    biascorr_kernel<<<dim3(C_ / 128, V_), 128, 0, s2>>>(attn1_w, norm3_b, attn1_b, p_bcorr);
    cudaMemsetAsync(p_cnt, 0, sizeof(int) * NSLOT_ * D2_, s2);
    cudaMemsetAsync(p_mcnt, 0, sizeof(int) * V_, s2);
    cudaMemsetAsync(p_mpos, 0xFF, sizeof(int) * V_ * TG_, s2);
    cudaMemsetAsync(p_stats, 0, sizeof(float) * NSLOT_ * 2 * C_, s2);
    hist_kernel<<<dim3(TG_ / 256, NSLOT_), 256, 0, s2>>>(fgi, cluster, p_cnt);
    scan_kernel<<<NSLOT_, 256, 0, s2>>>(p_cnt, p_off, p_fill);
    fillcsr_kernel<<<dim3(TG_ / 256, NSLOT_), 256, 0, s2>>>(fgi, cluster, p_fill, p_list);
    maskfill_kernel<<<dim3(TG_ / 256, V_), 256, 0, s2>>>(maskp, p_mcnt, p_mrows, p_mpos);
    cudaEventRecord(evB, s2);

    // ---- main chain
    ln_kernel<<<T_, 128>>>(x, ln1_g, ln1_b, p_ah);
    cudaStreamWaitEvent(0, evA, 0);
    tgemm(p_ah, p_wqkvT, nullptr, nullptr, nullptr, p_qh, T_, 3 * C_, C_, 0);
    fattn_kernel<<<dim3(9, H_, B_), 128>>>(p_qh, p_ah);
    cudaStreamWaitEvent(0, evC, 0);
    tgemm(p_ah, p_wprojT, proj_b, ls1_g, xout, nullptr, T_, C_, C_, 0);

    ln_kernel<<<T_, 128>>>(xout, ln2_g, ln2_b, p_ah);
    tgemm(p_ah, p_wfc1T, fc1_b, nullptr, nullptr, p_hh, T_, 4 * C_, C_, 1);
    tgemm(p_hh, p_wfc2T, fc2_b, nullptr, nullptr, p_ah, T_, C_, 4 * C_, 0);
    // fused adapter + residual + unit-gamma LN -> fp16 z + fp16 xpat
    adapterln_kernel<<<T_, 128>>>(p_ah, ls2_g, ad_down_w, ad_down_b, ad_up_w, ad_up_b,
                                  xout, p_zh, p_xpat);
    cudaEventRecord(evD, 0);

    // ---- slot-6 (cluster) pooling on s2, overlapping the view GEMM
    cudaStreamWaitEvent(s2, evD, 0);
    gatherB_kernel<<<dim3((NC_ + 3) / 4, 1), 128, 0, s2>>>(p_xpat, p_hlocC, p_mpos, p_off, p_cnt,
                                                           p_list, p_tv, p_t3, 6);
    seg_statsB_kernel<<<dim3(64, 1), C_, 0, s2>>>(p_tv, p_t3, p_stats, 6);
    cudaEventRecord(evE, s2);

    cudaStreamWaitEvent(0, evB, 0);
    // all 6 view GEMMs in one launch (masked rows only, fp16 single pass, fp16 out)
    tgemm_views_kernel<<<dim3(3, TG_ / 128, V_), 256, SMEM_DYN>>>(p_zh, p_wattnT,
                                                                  p_bcorr, p_mcnt, p_mrows, p_hlocC);

    // view-slot pooling + stats on main
    gatherB_kernel<<<dim3((D2_ + 3) / 4, 6), 128>>>(p_xpat, p_hlocC, p_mpos, p_off, p_cnt,
                                                    p_list, p_tv, p_t3, 0);
    seg_statsB_kernel<<<dim3(64, 6), C_>>>(p_tv, p_t3, p_stats, 0);
    cudaStreamWaitEvent(0, evE, 0);
    bnparam_kernel<<<NSLOT_, C_>>>(p_stats, bn2d_g, bn2d_b, bn3d_g, bn3d_b, p_bns, p_bnb);

    // cosine-weighted fusion (BN+gelu applied on the fly, fp16 tables)
    sims_kernel<<<(TG_ * 32 + 255) / 256, 256>>>(xout, cluster, fgi, p_t3, p_tv, p_bns, p_bnb);
}

// round 17
// speedup vs baseline: 1.0341x; 1.0285x over previous
#include <cuda_runtime.h>
#include <cuda_bf16.h>
#include <cuda_fp16.h>
#include <cfloat>
#include <cmath>
#include <cstdint>

// ---------------------------------------------------------------------------
// Problem constants
// ---------------------------------------------------------------------------
constexpr int B_  = 32;
constexpr int N_  = 513;      // G+1 tokens
constexpr int C_  = 384;
constexpr int H_  = 6;
constexpr int G_  = 512;
constexpr int V_  = 6;
constexpr int NC_ = 2048;     // N_CLUSTERS
constexpr int D2_ = 6272;     // B*GRID*GRID
constexpr int T_  = B_ * N_;  // 16416 tokens
constexpr int TG_ = B_ * G_;  // 16384 patch tokens
constexpr int NSLOT_ = 7;     // 6 views + cluster
constexpr float EPS_ = 1e-5f;

// ---------------------------------------------------------------------------
// Scratch (static device globals; no runtime allocation)
// ---------------------------------------------------------------------------
__device__ __half g_tv   [V_ * D2_ * C_];  // pooled t per view (fp16)
__device__ __half g_t3   [NC_ * C_];       // pooled t for cluster path (fp16)
__device__ float g_stats[NSLOT_ * 2 * C_];
__device__ float g_bns  [NSLOT_ * C_];     // BN scale per slot
__device__ float g_bnb  [NSLOT_ * C_];     // BN shift per slot
__device__ float g_bcorr[V_ * C_];

// CSR for segment pooling (slot 0..5 = views over fgi, slot 6 = cluster)
__device__ int g_cnt [NSLOT_ * D2_];
__device__ int g_off [NSLOT_ * D2_];
__device__ int g_fill[NSLOT_ * D2_];
__device__ int g_list[NSLOT_ * TG_];
// mask compaction
__device__ int g_mcnt [V_];
__device__ int g_mrows[V_ * TG_];
__device__ int g_mpos [V_ * TG_];

// bf16/fp16 staging
__device__ __nv_bfloat16 g_ah[T_ * C_];            // LN out / attn out / fc2 out (bf16)
__device__ __half        g_zh[TG_ * C_];           // unit-gamma LN of patch rows (fp16)
__device__ __half        g_xpat[TG_ * C_];         // compact patch xout rows (fp16)
__device__ __half        g_hlocC[V_ * TG_ * C_];   // compacted per-view hloc (fp16)
__device__ __nv_bfloat16 g_qh[T_ * 3 * C_];        // qkv bf16
__device__ __nv_bfloat16 g_hh[T_ * 4 * C_];        // fc1 out bf16
__device__ __nv_bfloat16 g_wqkvT[3 * C_ * C_];
__device__ __nv_bfloat16 g_wprojT[C_ * C_];
__device__ __nv_bfloat16 g_wfc1T [4 * C_ * C_];
__device__ __nv_bfloat16 g_wfc2T [C_ * 4 * C_];
__device__ __half        g_wattnT[V_ * C_ * C_];   // fp16 view weights

// ---------------------------------------------------------------------------
// Portable PTX helpers (sm_80+ baseline)
// ---------------------------------------------------------------------------
__device__ __forceinline__ uint32_t smem_u32(const void* p) {
    uint32_t a;
    asm("{ .reg .u64 t; cvta.to.shared.u64 t, %1; cvt.u32.u64 %0, t; }" : "=r"(a) : "l"(p));
    return a;
}
__device__ __forceinline__ void cpa16(uint32_t dst, const void* src, int sz) {
    asm volatile("cp.async.cg.shared.global [%0], [%1], 16, %2;"
                 :: "r"(dst), "l"(src), "r"(sz) : "memory");
}
#define CPA_COMMIT() asm volatile("cp.async.commit_group;" ::: "memory")
#define CPA_WAIT1()  asm volatile("cp.async.wait_group 1;" ::: "memory")
#define CPA_WAIT0()  asm volatile("cp.async.wait_group 0;" ::: "memory")

__device__ __forceinline__ void ldm_x4(uint32_t* r, uint32_t addr) {
    asm volatile("ldmatrix.sync.aligned.m8n8.x4.shared.b16 {%0,%1,%2,%3}, [%4];"
                 : "=r"(r[0]), "=r"(r[1]), "=r"(r[2]), "=r"(r[3]) : "r"(addr));
}
__device__ __forceinline__ void ldm_x4_trans(uint32_t* r, uint32_t addr) {
    asm volatile("ldmatrix.sync.aligned.m8n8.x4.trans.shared.b16 {%0,%1,%2,%3}, [%4];"
                 : "=r"(r[0]), "=r"(r[1]), "=r"(r[2]), "=r"(r[3]) : "r"(addr));
}
__device__ __forceinline__ void mma_bf16(float* c, const uint32_t* a, uint32_t b0, uint32_t b1) {
    asm volatile("mma.sync.aligned.m16n8k16.row.col.f32.bf16.bf16.f32 "
                 "{%0,%1,%2,%3}, {%4,%5,%6,%7}, {%8,%9}, {%0,%1,%2,%3};"
                 : "+f"(c[0]), "+f"(c[1]), "+f"(c[2]), "+f"(c[3])
                 : "r"(a[0]), "r"(a[1]), "r"(a[2]), "r"(a[3]), "r"(b0), "r"(b1));
}
__device__ __forceinline__ void mma_f16(float* c, const uint32_t* a, uint32_t b0, uint32_t b1) {
    asm volatile("mma.sync.aligned.m16n8k16.row.col.f32.f16.f16.f32 "
                 "{%0,%1,%2,%3}, {%4,%5,%6,%7}, {%8,%9}, {%0,%1,%2,%3};"
                 : "+f"(c[0]), "+f"(c[1]), "+f"(c[2]), "+f"(c[3])
                 : "r"(a[0]), "r"(a[1]), "r"(a[2]), "r"(a[3]), "r"(b0), "r"(b1));
}
__device__ __forceinline__ uint32_t packbf(float lo, float hi) {
    uint32_t r;
    asm("cvt.rn.bf16x2.f32 %0, %1, %2;" : "=r"(r) : "f"(hi), "f"(lo));
    return r;
}
__device__ __forceinline__ uint32_t packhf(float lo, float hi) {
    uint32_t r;
    asm("cvt.rn.f16x2.f32 %0, %1, %2;" : "=r"(r) : "f"(hi), "f"(lo));
    return r;
}

// ---------------------------------------------------------------------------
// Math helpers
// ---------------------------------------------------------------------------
__device__ __forceinline__ float geluf(float x) {
    return 0.5f * x * (1.0f + erff(x * 0.70710678118654752f));
}
__device__ __forceinline__ float warpSum(float v) {
    #pragma unroll
    for (int o = 16; o > 0; o >>= 1) v += __shfl_xor_sync(0xffffffffu, v, o);
    return v;
}

// ---------------------------------------------------------------------------
// bf16 HMMA GEMM, 3-stage cp.async pipeline, single barrier per K-iter.
// ---------------------------------------------------------------------------
constexpr int BM = 128, BN = 128, BK = 32;
constexpr int LDA = BK + 8;
constexpr int STAGE_ELEMS = BM * LDA + BN * LDA;   // 10240 elems = 20480 B
constexpr int SMEM_DYN = 3 * STAGE_ELEMS * 2;      // 61440 B

__global__ __launch_bounds__(256, 2)
void tgemm_kernel(const __nv_bfloat16* __restrict__ Ah,
                  const __nv_bfloat16* __restrict__ Bh,
                  const float* __restrict__ bias, const float* __restrict__ ls,
                  float* __restrict__ CoutF, __nv_bfloat16* __restrict__ outH,
                  int M, int Nn, int K, int doGelu)
{
    extern __shared__ __nv_bfloat16 smext[];
    uint32_t sbase = smem_u32(smext);

    int tid = threadIdx.x, lane = tid & 31, wid = tid >> 5;
    int wm = wid & 1, wn = wid >> 1;
    int m0 = blockIdx.y * BM, n0 = blockIdx.x * BN;

    const int total = K >> 5;

    float c[4][4][4];
    #pragma unroll
    for (int mi = 0; mi < 4; mi++)
        #pragma unroll
        for (int ni = 0; ni < 4; ni++)
            #pragma unroll
            for (int e = 0; e < 4; e++) c[mi][ni][e] = 0.0f;

    auto loadTiles = [&](int it, int s) {
        int k0 = it * BK;
        uint32_t aOff = sbase + (uint32_t)(s * STAGE_ELEMS) * 2;
        uint32_t bOff = aOff + (uint32_t)(BM * LDA) * 2;
        #pragma unroll
        for (int r = 0; r < 2; r++) {
            int idx = tid + r * 256;
            int row = idx >> 2;
            int ch  = (idx & 3) * 8;
            int gr  = m0 + row;
            int grc = gr < M ? gr : 0;
            cpa16(aOff + (uint32_t)(row * LDA + ch) * 2,
                  Ah + (size_t)grc * K + k0 + ch, gr < M ? 16 : 0);
            cpa16(bOff + (uint32_t)(row * LDA + ch) * 2,
                  Bh + (size_t)(n0 + row) * K + k0 + ch, 16);
        }
    };

    loadTiles(0, 0);
    CPA_COMMIT();
    if (total > 1) { loadTiles(1, 1); CPA_COMMIT(); }

    for (int it = 0; it < total; it++) {
        if (it + 1 < total) { CPA_WAIT1(); } else { CPA_WAIT0(); }
        __syncthreads();
        if (it + 2 < total) { loadTiles(it + 2, (it + 2) % 3); CPA_COMMIT(); }

        int cur = it % 3;
        uint32_t aB = sbase + (uint32_t)(cur * STAGE_ELEMS) * 2;
        uint32_t bB = aB + (uint32_t)(BM * LDA) * 2;

        #pragma unroll
        for (int k16 = 0; k16 < 2; k16++) {
            uint32_t a[4][4];
            #pragma unroll
            for (int mi = 0; mi < 4; mi++) {
                uint32_t addr = aB + (uint32_t)((wm * 64 + mi * 16 + (lane & 15)) * LDA
                                                + k16 * 16 + (lane >> 4) * 8) * 2;
                ldm_x4(a[mi], addr);
            }
            uint32_t b[2][4];
            #pragma unroll
            for (int bt = 0; bt < 2; bt++) {
                uint32_t addr = bB + (uint32_t)((wn * 32 + bt * 16 + (lane & 7) + ((lane >> 4) * 8)) * LDA
                                                + k16 * 16 + ((lane >> 3) & 1) * 8) * 2;
                ldm_x4(b[bt], addr);
            }
            #pragma unroll
            for (int mi = 0; mi < 4; mi++)
                #pragma unroll
                for (int ni = 0; ni < 4; ni++) {
                    const uint32_t* bb = b[ni >> 1];
                    int off = (ni & 1) * 2;
                    mma_bf16(c[mi][ni], a[mi], bb[off], bb[off + 1]);
                }
        }
    }

    int group = lane >> 2, qid = lane & 3;
    #pragma unroll
    for (int mi = 0; mi < 4; mi++) {
        #pragma unroll
        for (int ni = 0; ni < 4; ni++) {
            int col = n0 + wn * 32 + ni * 8 + qid * 2;
            #pragma unroll
            for (int half = 0; half < 2; half++) {
                int row = m0 + wm * 64 + mi * 16 + group + half * 8;
                if (row < M) {
                    float v0 = c[mi][ni][half * 2 + 0];
                    float v1 = c[mi][ni][half * 2 + 1];
                    if (bias) { v0 += bias[col]; v1 += bias[col + 1]; }
                    if (doGelu) { v0 = geluf(v0); v1 = geluf(v1); }
                    if (outH) {
                        *(uint32_t*)(outH + (size_t)row * Nn + col) = packbf(v0, v1);
                    } else {
                        float* cp = CoutF + (size_t)row * Nn + col;
                        if (ls) { cp[0] += ls[col] * v0; cp[1] += ls[col + 1] * v1; }
                        else    { cp[0] = v0; cp[1] = v1; }
                    }
                }
            }
        }
    }
}

// ---------------------------------------------------------------------------
// Batched per-view GEMM, fp16 single-pass, masked-row compaction,
// 3-stage pipeline, fp16 output. grid (3, 128, V).
// ---------------------------------------------------------------------------
__global__ __launch_bounds__(256, 2)
void tgemm_views_kernel(const __half* __restrict__ Zh,
                        const __half* __restrict__ WAll,
                        const float* __restrict__ bcorr, const int* __restrict__ mcnt,
                        const int* __restrict__ mrows, __half* __restrict__ hlocC)
{
    int v = blockIdx.z;
    int M = mcnt[v];
    int m0 = blockIdx.y * BM;
    if (m0 >= M) return;
    int n0 = blockIdx.x * BN;

    const __half* Bw = WAll + (size_t)v * C_ * C_;
    const float* bias = bcorr + v * C_;
    const int* rlist = mrows + v * TG_;
    __half* Cout = hlocC + (size_t)v * TG_ * C_;
    const int K = C_;

    extern __shared__ __nv_bfloat16 smext[];
    uint32_t sbase = smem_u32(smext);

    int tid = threadIdx.x, lane = tid & 31, wid = tid >> 5;
    int wm = wid & 1, wn = wid >> 1;

    const int total = K >> 5;            // 12

    float c[4][4][4];
    #pragma unroll
    for (int mi = 0; mi < 4; mi++)
        #pragma unroll
        for (int ni = 0; ni < 4; ni++)
            #pragma unroll
            for (int e = 0; e < 4; e++) c[mi][ni][e] = 0.0f;

    auto loadTiles = [&](int it, int s) {
        int k0 = it * BK;
        uint32_t aOff = sbase + (uint32_t)(s * STAGE_ELEMS) * 2;
        uint32_t bOff = aOff + (uint32_t)(BM * LDA) * 2;
        #pragma unroll
        for (int r = 0; r < 2; r++) {
            int idx = tid + r * 256;
            int row = idx >> 2;
            int ch  = (idx & 3) * 8;
            int rr  = m0 + row;
            int gr  = rr < M ? rlist[rr] : 0;
            cpa16(aOff + (uint32_t)(row * LDA + ch) * 2,
                  Zh + (size_t)gr * K + k0 + ch, rr < M ? 16 : 0);
            cpa16(bOff + (uint32_t)(row * LDA + ch) * 2,
                  Bw + (size_t)(n0 + row) * K + k0 + ch, 16);
        }
    };

    loadTiles(0, 0);
    CPA_COMMIT();
    loadTiles(1, 1);
    CPA_COMMIT();

    for (int it = 0; it < total; it++) {
        if (it + 1 < total) { CPA_WAIT1(); } else { CPA_WAIT0(); }
        __syncthreads();
        if (it + 2 < total) { loadTiles(it + 2, (it + 2) % 3); CPA_COMMIT(); }

        int cur = it % 3;
        uint32_t aB = sbase + (uint32_t)(cur * STAGE_ELEMS) * 2;
        uint32_t bB = aB + (uint32_t)(BM * LDA) * 2;

        #pragma unroll
        for (int k16 = 0; k16 < 2; k16++) {
            uint32_t a[4][4];
            #pragma unroll
            for (int mi = 0; mi < 4; mi++) {
                uint32_t addr = aB + (uint32_t)((wm * 64 + mi * 16 + (lane & 15)) * LDA
                                                + k16 * 16 + (lane >> 4) * 8) * 2;
                ldm_x4(a[mi], addr);
            }
            uint32_t b[2][4];
            #pragma unroll
            for (int bt = 0; bt < 2; bt++) {
                uint32_t addr = bB + (uint32_t)((wn * 32 + bt * 16 + (lane & 7) + ((lane >> 4) * 8)) * LDA
                                                + k16 * 16 + ((lane >> 3) & 1) * 8) * 2;
                ldm_x4(b[bt], addr);
            }
            #pragma unroll
            for (int mi = 0; mi < 4; mi++)
                #pragma unroll
                for (int ni = 0; ni < 4; ni++) {
                    const uint32_t* bb = b[ni >> 1];
                    int off = (ni & 1) * 2;
                    mma_f16(c[mi][ni], a[mi], bb[off], bb[off + 1]);
                }
        }
    }

    int group = lane >> 2, qid = lane & 3;
    #pragma unroll
    for (int mi = 0; mi < 4; mi++) {
        #pragma unroll
        for (int ni = 0; ni < 4; ni++) {
            int col = n0 + wn * 32 + ni * 8 + qid * 2;
            #pragma unroll
            for (int half = 0; half < 2; half++) {
                int row = m0 + wm * 64 + mi * 16 + group + half * 8;
                if (row < M) {
                    float v0 = c[mi][ni][half * 2 + 0] + bias[col];
                    float v1 = c[mi][ni][half * 2 + 1] + bias[col + 1];
                    *(uint32_t*)(Cout + (size_t)row * C_ + col) = packhf(v0, v1);
                }
            }
        }
    }
}

// ---------------------------------------------------------------------------
// Flash attention, bf16 HMMA (validated best config: 64q/128thr, static smem).
// ---------------------------------------------------------------------------
constexpr int LDQK = 72;

__global__ __launch_bounds__(128)
void fattn_kernel(const __nv_bfloat16* __restrict__ qkv, __nv_bfloat16* __restrict__ outH)
{
    __shared__ __nv_bfloat16 sQ[64 * LDQK], sK[64 * LDQK], sV[64 * LDQK];
    int tid = threadIdx.x, lane = tid & 31, wid = tid >> 5;
    int qt = blockIdx.x, h = blockIdx.y, b = blockIdx.z;
    size_t base = (size_t)b * N_ * 1152;

    #pragma unroll
    for (int it = 0; it < 4; it++) {
        int idx = tid + it * 128;
        int row = idx >> 3, seg = idx & 7;
        int qi = qt * 64 + row; if (qi > N_ - 1) qi = N_ - 1;
        *(uint4*)&sQ[row * LDQK + seg * 8] =
            *(const uint4*)(qkv + base + (size_t)qi * 1152 + h * 64 + seg * 8);
    }
    __syncthreads();

    uint32_t sqb = smem_u32(sQ), skb = smem_u32(sK), svb = smem_u32(sV);
    uint32_t aQ[4][4];
    #pragma unroll
    for (int k16 = 0; k16 < 4; k16++) {
        uint32_t addr = sqb + (uint32_t)((wid * 16 + (lane & 15)) * LDQK
                                         + k16 * 16 + (lane >> 4) * 8) * 2;
        ldm_x4(aQ[k16], addr);
    }

    float o[8][4];
    #pragma unroll
    for (int ch = 0; ch < 8; ch++)
        #pragma unroll
        for (int e = 0; e < 4; e++) o[ch][e] = 0.0f;
    float m0 = -1e30f, m1 = -1e30f, l0 = 0.0f, l1 = 0.0f;
    int q2 = (lane & 3) * 2;

    for (int kt = 0; kt < 9; kt++) {
        __syncthreads();
        #pragma unroll
        for (int it = 0; it < 4; it++) {
            int idx = tid + it * 128;
            int row = idx >> 3, seg = idx & 7;
            int kv = kt * 64 + row; if (kv > N_ - 1) kv = N_ - 1;
            const __nv_bfloat16* src = qkv + base + (size_t)kv * 1152 + 384 + h * 64 + seg * 8;
            *(uint4*)&sK[row * LDQK + seg * 8] = *(const uint4*)src;
            *(uint4*)&sV[row * LDQK + seg * 8] = *(const uint4*)(src + 384);
        }
        __syncthreads();

        float s[8][4];
        #pragma unroll
        for (int ch = 0; ch < 8; ch++)
            #pragma unroll
            for (int e = 0; e < 4; e++) s[ch][e] = 0.0f;
        #pragma unroll
        for (int ng = 0; ng < 4; ng++) {
            #pragma unroll
            for (int k16 = 0; k16 < 4; k16++) {
                uint32_t bk[4];
                uint32_t addr = skb + (uint32_t)((ng * 16 + (lane & 7) + ((lane >> 4) * 8)) * LDQK
                                                 + k16 * 16 + ((lane >> 3) & 1) * 8) * 2;
                ldm_x4(bk, addr);
                mma_bf16(s[2 * ng],     aQ[k16], bk[0], bk[1]);
                mma_bf16(s[2 * ng + 1], aQ[k16], bk[2], bk[3]);
            }
        }

        float lm0 = -1e30f, lm1 = -1e30f;
        #pragma unroll
        for (int ch = 0; ch < 8; ch++) {
            int j = kt * 64 + ch * 8 + q2;
            #pragma unroll
            for (int e = 0; e < 4; e++) s[ch][e] *= 0.125f;
            if (j >= N_)     { s[ch][0] = -1e30f; s[ch][2] = -1e30f; }
            if (j + 1 >= N_) { s[ch][1] = -1e30f; s[ch][3] = -1e30f; }
            lm0 = fmaxf(lm0, fmaxf(s[ch][0], s[ch][1]));
            lm1 = fmaxf(lm1, fmaxf(s[ch][2], s[ch][3]));
        }
        lm0 = fmaxf(lm0, __shfl_xor_sync(0xffffffffu, lm0, 1));
        lm0 = fmaxf(lm0, __shfl_xor_sync(0xffffffffu, lm0, 2));
        lm1 = fmaxf(lm1, __shfl_xor_sync(0xffffffffu, lm1, 1));
        lm1 = fmaxf(lm1, __shfl_xor_sync(0xffffffffu, lm1, 2));
        float mn0 = fmaxf(m0, lm0), mn1 = fmaxf(m1, lm1);
        float c0f = __expf(m0 - mn0), c1f = __expf(m1 - mn1);
        l0 *= c0f; l1 *= c1f;
        #pragma unroll
        for (int ch = 0; ch < 8; ch++) {
            o[ch][0] *= c0f; o[ch][1] *= c0f; o[ch][2] *= c1f; o[ch][3] *= c1f;
        }
        uint32_t P[8][2];
        float ls0 = 0.0f, ls1 = 0.0f;
        #pragma unroll
        for (int ch = 0; ch < 8; ch++) {
            float p0 = __expf(s[ch][0] - mn0), p1 = __expf(s[ch][1] - mn0);
            float p2 = __expf(s[ch][2] - mn1), p3 = __expf(s[ch][3] - mn1);
            ls0 += p0 + p1; ls1 += p2 + p3;
            P[ch][0] = packbf(p0, p1);
            P[ch][1] = packbf(p2, p3);
        }
        ls0 += __shfl_xor_sync(0xffffffffu, ls0, 1);
        ls0 += __shfl_xor_sync(0xffffffffu, ls0, 2);
        ls1 += __shfl_xor_sync(0xffffffffu, ls1, 1);
        ls1 += __shfl_xor_sync(0xffffffffu, ls1, 2);
        l0 += ls0; l1 += ls1; m0 = mn0; m1 = mn1;

        #pragma unroll
        for (int dg = 0; dg < 4; dg++) {
            #pragma unroll
            for (int k16 = 0; k16 < 4; k16++) {
                uint32_t bv[4];
                uint32_t addr = svb + (uint32_t)((k16 * 16 + (lane & 15)) * LDQK
                                                 + dg * 16 + (lane >> 4) * 8) * 2;
                ldm_x4_trans(bv, addr);
                uint32_t ap[4] = {P[2 * k16][0], P[2 * k16][1],
                                  P[2 * k16 + 1][0], P[2 * k16 + 1][1]};
                mma_bf16(o[2 * dg],     ap, bv[0], bv[1]);
                mma_bf16(o[2 * dg + 1], ap, bv[2], bv[3]);
            }
        }
    }

    float i0 = 1.0f / l0, i1 = 1.0f / l1;
    int g = lane >> 2;
    int r0 = qt * 64 + wid * 16 + g, r1 = r0 + 8;
    #pragma unroll
    for (int ch = 0; ch < 8; ch++) {
        int col = h * 64 + ch * 8 + q2;
        if (r0 < N_)
            *(uint32_t*)(outH + (size_t)(b * N_ + r0) * C_ + col) = packbf(o[ch][0] * i0, o[ch][1] * i0);
        if (r1 < N_)
            *(uint32_t*)(outH + (size_t)(b * N_ + r1) * C_ + col) = packbf(o[ch][2] * i1, o[ch][3] * i1);
    }
}

// ---------------------------------------------------------------------------
// Weight transpose: bf16 (main GEMMs) and fp16 w/ row scale (views)
// ---------------------------------------------------------------------------
__global__ void transW_kernel(const float* __restrict__ W,
                              __nv_bfloat16* __restrict__ hiT, int K, int N)
{
    __shared__ float t[32][33];
    int n0 = blockIdx.x * 32, k0 = blockIdx.y * 32;
    int tx = threadIdx.x, ty = threadIdx.y;
    #pragma unroll
    for (int r = 0; r < 4; r++)
        t[ty + 8 * r][tx] = W[(size_t)(k0 + ty + 8 * r) * N + n0 + tx];
    __syncthreads();
    #pragma unroll
    for (int r = 0; r < 4; r++) {
        int nl = ty + 8 * r;
        hiT[(size_t)(n0 + nl) * K + k0 + tx] = __float2bfloat16(t[tx][nl]);
    }
}

__global__ void transWh_kernel(const float* __restrict__ W, const float* __restrict__ g,
                               __half* __restrict__ outT, int K, int N)
{
    __shared__ float t[32][33];
    int n0 = blockIdx.x * 32, k0 = blockIdx.y * 32;
    int tx = threadIdx.x, ty = threadIdx.y;
    #pragma unroll
    for (int r = 0; r < 4; r++)
        t[ty + 8 * r][tx] = W[(size_t)(k0 + ty + 8 * r) * N + n0 + tx];
    __syncthreads();
    float gs = g[k0 + tx];
    #pragma unroll
    for (int r = 0; r < 4; r++) {
        int nl = ty + 8 * r;
        outT[(size_t)(n0 + nl) * K + k0 + tx] = __float2half_rn(t[tx][nl] * gs);
    }
}

// ---------------------------------------------------------------------------
__global__ void biascorr_kernel(const float* __restrict__ attnW, const float* __restrict__ nb,
                                const float* __restrict__ ab, float* __restrict__ bc)
{
    int v = blockIdx.y;
    int n = blockIdx.x * 128 + threadIdx.x;
    const float* W = attnW + (size_t)v * C_ * C_;
    const float* b = nb + v * C_;
    float s = 0.0f;
    for (int k = 0; k < C_; k++) s += b[k] * W[(size_t)k * C_ + n];
    bc[v * C_ + n] = ab[v * C_ + n] + s;
}

// ---------------------------------------------------------------------------
// CSR build + mask compaction
// ---------------------------------------------------------------------------
__global__ void hist_kernel(const int* __restrict__ fgi, const int* __restrict__ cluster,
                            int* __restrict__ cnt)
{
    int v = blockIdx.y;
    int r = blockIdx.x * 256 + threadIdx.x;
    if (r >= TG_) return;
    int idx = (v < 6) ? fgi[v * TG_ + r] : cluster[r];
    atomicAdd(&cnt[v * D2_ + idx], 1);
}

__global__ void scan_kernel(const int* __restrict__ cnt, int* __restrict__ off,
                            int* __restrict__ fill)
{
    int v = blockIdx.x;
    int R = (v == 6) ? NC_ : D2_;
    const int* c = cnt + v * D2_;
    int* o = off + v * D2_;
    int* f = fill + v * D2_;
    __shared__ int part[256];
    int tid = threadIdx.x;
    int per = (R + 255) / 256;
    int base = tid * per;
    int s = 0;
    for (int i = 0; i < per; i++) { int j = base + i; if (j < R) s += c[j]; }
    part[tid] = s;
    __syncthreads();
    if (tid == 0) {
        int acc = 0;
        for (int i = 0; i < 256; i++) { int t = part[i]; part[i] = acc; acc += t; }
    }
    __syncthreads();
    int acc = part[tid];
    for (int i = 0; i < per; i++) {
        int j = base + i;
        if (j < R) { o[j] = acc; f[j] = acc; acc += c[j]; }
    }
}

__global__ void fillcsr_kernel(const int* __restrict__ fgi, const int* __restrict__ cluster,
                               int* __restrict__ fill, int* __restrict__ list)
{
    int v = blockIdx.y;
    int r = blockIdx.x * 256 + threadIdx.x;
    if (r >= TG_) return;
    int idx = (v < 6) ? fgi[v * TG_ + r] : cluster[r];
    int p = atomicAdd(&fill[v * D2_ + idx], 1);
    list[v * TG_ + p] = r;
}

__global__ void maskfill_kernel(const int* __restrict__ maskp, int* __restrict__ mcnt,
                                int* __restrict__ mrows, int* __restrict__ mpos)
{
    int v = blockIdx.y;
    int r = blockIdx.x * 256 + threadIdx.x;
    if (r >= TG_) return;
    if (maskp[v * TG_ + r]) {
        int p = atomicAdd(&mcnt[v], 1);
        mrows[v * TG_ + p] = r;
        mpos[v * TG_ + r] = p;
    }
}

// ---------------------------------------------------------------------------
// Batched gather-pool: warp per segment, 4 segments per block, fp16 in/out.
// ---------------------------------------------------------------------------
__global__ __launch_bounds__(128)
void gatherB_kernel(const __half* __restrict__ xpat, const __half* __restrict__ hlocC,
                    const int* __restrict__ mpos,
                    const int* __restrict__ off, const int* __restrict__ cnt,
                    const int* __restrict__ list,
                    __half* __restrict__ tv, __half* __restrict__ t3)
{
    int slot = blockIdx.y;
    int warp = threadIdx.x >> 5, lane = threadIdx.x & 31;
    int j = blockIdx.x * 4 + warp;
    int R = (slot == 6) ? NC_ : D2_;
    if (j >= R) return;
    int base = off[slot * D2_ + j];
    int k = cnt[slot * D2_ + j];
    const int* rows = list + slot * TG_ + base;
    const __half2* xp2 = (const __half2*)xpat;
    const __half2* hC2 = (const __half2*)(hlocC + (size_t)slot * TG_ * C_);
    const int* mp = mpos + slot * TG_;

    float mxx[6], mxy[6], sx[6], sy[6];
    #pragma unroll
    for (int kk = 0; kk < 6; kk++) { mxx[kk] = -FLT_MAX; mxy[kk] = -FLT_MAX; sx[kk] = 0.0f; sy[kk] = 0.0f; }

    for (int i = 0; i < k; i++) {
        int r = rows[i];
        const __half2* src = xp2 + (size_t)r * 192;
        int p = (slot < 6) ? mp[r] : -1;
        if (p >= 0) {
            const __half2* hp = hC2 + (size_t)p * 192;
            #pragma unroll
            for (int kk = 0; kk < 6; kk++) {
                float2 v = __half22float2(src[lane + 32 * kk]);
                float2 h = __half22float2(hp[lane + 32 * kk]);
                v.x += h.x; v.y += h.y;
                mxx[kk] = fmaxf(mxx[kk], v.x); mxy[kk] = fmaxf(mxy[kk], v.y);
                sx[kk] += v.x; sy[kk] += v.y;
            }
        } else {
            #pragma unroll
            for (int kk = 0; kk < 6; kk++) {
                float2 v = __half22float2(src[lane + 32 * kk]);
                mxx[kk] = fmaxf(mxx[kk], v.x); mxy[kk] = fmaxf(mxy[kk], v.y);
                sx[kk] += v.x; sy[kk] += v.y;
            }
        }
    }

    __half* tp = (slot == 6) ? (t3 + (size_t)j * C_)
                             : (tv + ((size_t)slot * D2_ + j) * C_);
    if (k > 0) {
        float inv = 1.0f / (float)k;
        #pragma unroll
        for (int kk = 0; kk < 6; kk++) {
            *(uint32_t*)(tp + 2 * (lane + 32 * kk)) =
                packhf(mxx[kk] + sx[kk] * inv, mxy[kk] + sy[kk] * inv);
        }
    } else {
        #pragma unroll
        for (int kk = 0; kk < 6; kk++)
            *(uint32_t*)(tp + 2 * (lane + 32 * kk)) = 0u;
    }
}

// ---------------------------------------------------------------------------
__global__ void seg_statsB_kernel(const __half* __restrict__ tv, const __half* __restrict__ t3,
                                  float* __restrict__ stat)
{
    int slot = blockIdx.y;
    int R = (slot == 6) ? NC_ : D2_;
    const __half* t = (slot == 6) ? t3 : tv + (size_t)slot * D2_ * C_;
    float* st = stat + slot * 2 * C_;
    int c = threadIdx.x;  // 384
    int rows_per = (R + gridDim.x - 1) / gridDim.x;
    int r0 = blockIdx.x * rows_per;
    int r1 = r0 + rows_per; if (r1 > R) r1 = R;
    float s1 = 0.0f, s2 = 0.0f;
    for (int r = r0; r < r1; r++) {
        float v = __half2float(t[(size_t)r * C_ + c]);
        s1 += v; s2 += v * v;
    }
    atomicAdd(&st[c], s1);
    atomicAdd(&st[C_ + c], s2);
}

// ---------------------------------------------------------------------------
__global__ void bnparam_kernel(const float* __restrict__ stat,
                               const float* __restrict__ bn2d_g, const float* __restrict__ bn2d_b,
                               const float* __restrict__ bn3d_g, const float* __restrict__ bn3d_b,
                               float* __restrict__ bns, float* __restrict__ bnb)
{
    int slot = blockIdx.x;
    int c = threadIdx.x;
    int R = (slot == 6) ? NC_ : D2_;
    const float* st = stat + slot * 2 * C_;
    float mean = st[c] / (float)R;
    float var  = fmaxf(st[C_ + c] / (float)R - mean * mean, 0.0f);
    float g = (slot == 6) ? bn3d_g[c] : bn2d_g[slot * C_ + c];
    float b = (slot == 6) ? bn3d_b[c] : bn2d_b[slot * C_ + c];
    float sc = g * rsqrtf(var + EPS_);
    bns[slot * C_ + c] = sc;
    bnb[slot * C_ + c] = b - mean * sc;
}

// ---------------------------------------------------------------------------
// LayerNorm over C -> bf16 (warp-shuffle reduction, single barrier)
// ---------------------------------------------------------------------------
__global__ void ln_kernel(const float* __restrict__ in,
                          const float* __restrict__ gam,
                          const float* __restrict__ bet,
                          __nv_bfloat16* __restrict__ outHi)
{
    int r = blockIdx.x;
    int tid = threadIdx.x;   // 128
    int wid = tid >> 5, lane = tid & 31;
    const float* row = in + (size_t)r * C_;
    float v0 = row[tid], v1 = row[tid + 128], v2 = row[tid + 256];
    float s1 = v0 + v1 + v2;
    float s2 = v0 * v0 + v1 * v1 + v2 * v2;
    s1 = warpSum(s1);
    s2 = warpSum(s2);
    __shared__ float a1[4], a2[4];
    if (lane == 0) { a1[wid] = s1; a2[wid] = s2; }
    __syncthreads();
    float t1 = a1[0] + a1[1] + a1[2] + a1[3];
    float t2 = a2[0] + a2[1] + a2[2] + a2[3];
    float mean = t1 / C_;
    float var  = fmaxf(t2 / C_ - mean * mean, 0.0f);
    float inv  = rsqrtf(var + EPS_);
    #pragma unroll
    for (int k = 0; k < 3; k++) {
        int c = tid + 128 * k;
        float vv = (k == 0) ? v0 : (k == 1) ? v1 : v2;
        float y = (vv - mean) * inv;
        y = y * gam[c] + bet[c];
        outHi[(size_t)r * C_ + c] = __float2bfloat16(y);
    }
}

// ---------------------------------------------------------------------------
// Fused adapter + residual + unit-gamma LN -> fp16 z + fp16 compact xpat.
// Warp-shuffle LN reduction (single barrier for that phase).
// ---------------------------------------------------------------------------
__global__ void adapterln_kernel(const __nv_bfloat16* __restrict__ fc2out,
                                 const float* __restrict__ ls2,
                                 const float* __restrict__ dw, const float* __restrict__ db,
                                 const float* __restrict__ uw, const float* __restrict__ ub,
                                 float* __restrict__ xout, __half* __restrict__ zh,
                                 __half* __restrict__ xpat)
{
    int t = blockIdx.x;
    int tid = threadIdx.x;  // 128
    __shared__ float xf[C_];
    __shared__ float h16[16];
    __shared__ float a1[4], a2[4];
    #pragma unroll
    for (int k = 0; k < 3; k++) {
        int c = tid + 128 * k;
        xf[c] = ls2[c] * __bfloat162float(fc2out[(size_t)t * C_ + c]);
    }
    __syncthreads();
    int wid = tid >> 5, lane = tid & 31;
    #pragma unroll
    for (int jj = 0; jj < 4; jj++) {
        int j = wid * 4 + jj;
        float p = 0.0f;
        #pragma unroll
        for (int k = 0; k < 12; k++) {
            int c = lane + 32 * k;
            p += xf[c] * dw[c * 16 + j];
        }
        p = warpSum(p);
        if (lane == 0) h16[j] = geluf(p + db[j]);
    }
    __syncthreads();
    float nv[3];
    float s1 = 0.0f, s2 = 0.0f;
    #pragma unroll
    for (int k = 0; k < 3; k++) {
        int c = tid + 128 * k;
        float a = ub[c];
        #pragma unroll
        for (int j = 0; j < 16; j++) a += h16[j] * uw[j * C_ + c];
        float v = xout[(size_t)t * C_ + c] + xf[c] + 0.5f * a;
        xout[(size_t)t * C_ + c] = v;
        nv[k] = v;
        s1 += v; s2 += v * v;
    }
    s1 = warpSum(s1);
    s2 = warpSum(s2);
    if (lane == 0) { a1[wid] = s1; a2[wid] = s2; }
    __syncthreads();
    int bb = t / N_, idx = t - bb * N_;
    if (idx == 0) return;               // CLS token: no z/xpat
    float t1 = a1[0] + a1[1] + a1[2] + a1[3];
    float t2 = a2[0] + a2[1] + a2[2] + a2[3];
    float mean = t1 / C_;
    float var  = fmaxf(t2 / C_ - mean * mean, 0.0f);
    float inv  = rsqrtf(var + EPS_);
    size_t zr = (size_t)(bb * G_ + idx - 1) * C_;
    #pragma unroll
    for (int k = 0; k < 3; k++) {
        int c = tid + 128 * k;
        zh[zr + c]   = __float2half_rn((nv[k] - mean) * inv);
        xpat[zr + c] = __float2half_rn(nv[k]);
    }
}

// ---------------------------------------------------------------------------
// Final fusion: BN+gelu applied on the fly from fp16 pooled tables.
// ---------------------------------------------------------------------------
__global__ void sims_kernel(float* __restrict__ xout, const int* __restrict__ cluster,
                            const int* __restrict__ fgi,
                            const __half* __restrict__ t3, const __half* __restrict__ tv,
                            const float* __restrict__ bns, const float* __restrict__ bnb)
{
    int gw = (blockIdx.x * blockDim.x + threadIdx.x) >> 5;
    int lane = threadIdx.x & 31;
    if (gw >= TG_) return;
    int r = gw;
    int bb = r >> 9, gg = r & 511;
    size_t tok = (size_t)(bb * N_ + 1 + gg) * C_;

    float xr[12];
    const __half* xp = t3 + (size_t)cluster[r] * C_;
    float nx = 0.0f;
    #pragma unroll
    for (int k = 0; k < 12; k++) {
        int c = lane + 32 * k;
        float y = geluf(__half2float(xp[c]) * bns[6 * C_ + c] + bnb[6 * C_ + c]);
        xr[k] = y; nx += y * y;
    }
    nx = warpSum(nx);
    float nrmx = fmaxf(sqrtf(nx), 1e-8f);

    float d2[6][12];
    float w[6];
    float wsum = 0.0f;
    #pragma unroll
    for (int v = 0; v < 6; v++) {
        int ij = fgi[v * TG_ + r];
        const __half* dp = tv + ((size_t)v * D2_ + ij) * C_;
        float dot = 0.0f, nd = 0.0f;
        #pragma unroll
        for (int k = 0; k < 12; k++) {
            int c = lane + 32 * k;
            float dv = geluf(__half2float(dp[c]) * bns[v * C_ + c] + bnb[v * C_ + c]);
            d2[v][k] = dv;
            dot += dv * xr[k];
            nd  += dv * dv;
        }
        dot = warpSum(dot);
        nd  = warpSum(nd);
        float cosv = dot / (fmaxf(sqrtf(nd), 1e-8f) * nrmx);
        w[v] = (cosv + 1.0f) * 0.5f;
        wsum += w[v];
    }
    float inv = 1.0f / wsum;
    #pragma unroll
    for (int k = 0; k < 12; k++) {
        float a = 0.0f;
        #pragma unroll
        for (int v = 0; v < 6; v++) a += w[v] * d2[v][k];
        xout[tok + lane + 32 * k] += a * inv;   // COEF_PRO = 1
    }
}

// ---------------------------------------------------------------------------
// Host launcher
// ---------------------------------------------------------------------------
static float* symF(const void* sym) { void* p = nullptr; cudaGetSymbolAddress(&p, sym); return (float*)p; }
static int*   symI(const void* sym) { void* p = nullptr; cudaGetSymbolAddress(&p, sym); return (int*)p; }
static __nv_bfloat16* symH(const void* sym) { void* p = nullptr; cudaGetSymbolAddress(&p, sym); return (__nv_bfloat16*)p; }
static __half* symX(const void* sym) { void* p = nullptr; cudaGetSymbolAddress(&p, sym); return (__half*)p; }

static void tgemm(const __nv_bfloat16* Ah, const __nv_bfloat16* Bh,
                  const float* bias, const float* ls, float* CoutF, __nv_bfloat16* outH,
                  int M, int Nn, int K, int doGelu)
{
    dim3 grid(Nn / 128, (M + 127) / 128);
    tgemm_kernel<<<grid, 256, SMEM_DYN>>>(Ah, Bh, bias, ls, CoutF, outH, M, Nn, K, doGelu);
}

extern "C" void kernel_launch(void* const* d_in, const int* in_sizes, int n_in,
                              void* d_out, int out_size)
{
    (void)n_in; (void)out_size;
    const float *x, *ln1_g, *ln1_b, *qkv_w, *proj_w, *proj_b, *ls1_g, *ln2_g, *ln2_b,
        *fc1_w, *fc1_b, *fc2_w, *fc2_b, *ls2_g, *ad_down_w, *ad_down_b, *ad_up_w, *ad_up_b,
        *bn3d_g, *bn3d_b, *norm3_g, *norm3_b, *attn1_w, *attn1_b, *bn2d_g, *bn2d_b;
    const int *cluster, *fgi, *maskp;
    x = (const float*)d_in[0];
    const float** fps[25] = {&ln1_g,&ln1_b,&qkv_w,&proj_w,&proj_b,&ls1_g,&ln2_g,&ln2_b,
                             &fc1_w,&fc1_b,&fc2_w,&fc2_b,&ls2_g,&ad_down_w,&ad_down_b,
                             &ad_up_w,&ad_up_b,&bn3d_g,&bn3d_b,&norm3_g,&norm3_b,
                             &attn1_w,&attn1_b,&bn2d_g,&bn2d_b};
    if (in_sizes[1] == TG_) {
        cluster = (const int*)d_in[1];
        fgi     = (const int*)d_in[2];
        maskp   = (const int*)d_in[3];
        for (int i = 0; i < 25; i++) *fps[i] = (const float*)d_in[4 + i];
    } else {
        for (int i = 0; i < 25; i++) *fps[i] = (const float*)d_in[1 + i];
        cluster = (const int*)d_in[26];
        fgi     = (const int*)d_in[27];
        maskp   = (const int*)d_in[28];
    }
    float* xout = (float*)d_out;

    float *p_stats = symF(g_stats), *p_bns = symF(g_bns), *p_bnb = symF(g_bnb),
          *p_bcorr = symF(g_bcorr);
    int *p_cnt = symI(g_cnt), *p_off = symI(g_off), *p_fill = symI(g_fill), *p_list = symI(g_list);
    int *p_mcnt = symI(g_mcnt), *p_mrows = symI(g_mrows), *p_mpos = symI(g_mpos);
    __nv_bfloat16 *p_ah = symH(g_ah), *p_qh = symH(g_qh), *p_hh = symH(g_hh),
                  *p_wqkvT = symH(g_wqkvT), *p_wprojT = symH(g_wprojT),
                  *p_wfc1T = symH(g_wfc1T), *p_wfc2T = symH(g_wfc2T);
    __half *p_zh = symX(g_zh), *p_xpat = symX(g_xpat), *p_hlocC = symX(g_hlocC),
           *p_wattnT = symX(g_wattnT), *p_tv = symX(g_tv), *p_t3 = symX(g_t3);

    // one-time handles (host-side only; GPU work identical every call)
    static cudaStream_t s2 = nullptr;
    static cudaEvent_t ev0 = nullptr, evA = nullptr, evB = nullptr, evC = nullptr;
    if (!s2) {
        cudaStreamCreateWithFlags(&s2, cudaStreamNonBlocking);
        cudaEventCreateWithFlags(&ev0, cudaEventDisableTiming);
        cudaEventCreateWithFlags(&evA, cudaEventDisableTiming);
        cudaEventCreateWithFlags(&evB, cudaEventDisableTiming);
        cudaEventCreateWithFlags(&evC, cudaEventDisableTiming);
        cudaFuncSetAttribute(tgemm_kernel, cudaFuncAttributeMaxDynamicSharedMemorySize, SMEM_DYN);
        cudaFuncSetAttribute(tgemm_views_kernel, cudaFuncAttributeMaxDynamicSharedMemorySize, SMEM_DYN);
    }

    // ---- fork side stream for setup (weights, memcpy, CSR)
    cudaEventRecord(ev0, 0);
    cudaStreamWaitEvent(s2, ev0, 0);

    dim3 tb(32, 8);
    transW_kernel<<<dim3(3 * C_ / 32, C_ / 32), tb, 0, s2>>>(qkv_w, p_wqkvT, C_, 3 * C_);
    transW_kernel<<<dim3(C_ / 32, C_ / 32), tb, 0, s2>>>(proj_w, p_wprojT, C_, C_);
    transW_kernel<<<dim3(4 * C_ / 32, C_ / 32), tb, 0, s2>>>(fc1_w, p_wfc1T, C_, 4 * C_);
    transW_kernel<<<dim3(C_ / 32, 4 * C_ / 32), tb, 0, s2>>>(fc2_w, p_wfc2T, 4 * C_, C_);
    cudaEventRecord(evA, s2);

    cudaMemcpyAsync(xout, x, sizeof(float) * (size_t)T_ * C_, cudaMemcpyDeviceToDevice, s2);
    cudaEventRecord(evC, s2);

    for (int v = 0; v < V_; v++)
        transWh_kernel<<<dim3(C_ / 32, C_ / 32), tb, 0, s2>>>(attn1_w + (size_t)v * C_ * C_,
                                                              norm3_g + v * C_,
                                                              p_wattnT + (size_t)v * C_ * C_, C_, C_);
    biascorr_kernel<<<dim3(C_ / 128, V_), 128, 0, s2>>>(attn1_w, norm3_b, attn1_b, p_bcorr);
    cudaMemsetAsync(p_cnt, 0, sizeof(int) * NSLOT_ * D2_, s2);
    cudaMemsetAsync(p_mcnt, 0, sizeof(int) * V_, s2);
    cudaMemsetAsync(p_mpos, 0xFF, sizeof(int) * V_ * TG_, s2);
    cudaMemsetAsync(p_stats, 0, sizeof(float) * NSLOT_ * 2 * C_, s2);
    hist_kernel<<<dim3(TG_ / 256, NSLOT_), 256, 0, s2>>>(fgi, cluster, p_cnt);
    scan_kernel<<<NSLOT_, 256, 0, s2>>>(p_cnt, p_off, p_fill);
    fillcsr_kernel<<<dim3(TG_ / 256, NSLOT_), 256, 0, s2>>>(fgi, cluster, p_fill, p_list);
    maskfill_kernel<<<dim3(TG_ / 256, V_), 256, 0, s2>>>(maskp, p_mcnt, p_mrows, p_mpos);
    cudaEventRecord(evB, s2);

    // ---- main chain
    ln_kernel<<<T_, 128>>>(x, ln1_g, ln1_b, p_ah);
    cudaStreamWaitEvent(0, evA, 0);
    tgemm(p_ah, p_wqkvT, nullptr, nullptr, nullptr, p_qh, T_, 3 * C_, C_, 0);
    fattn_kernel<<<dim3(9, H_, B_), 128>>>(p_qh, p_ah);
    cudaStreamWaitEvent(0, evC, 0);
    tgemm(p_ah, p_wprojT, proj_b, ls1_g, xout, nullptr, T_, C_, C_, 0);

    ln_kernel<<<T_, 128>>>(xout, ln2_g, ln2_b, p_ah);
    tgemm(p_ah, p_wfc1T, fc1_b, nullptr, nullptr, p_hh, T_, 4 * C_, C_, 1);
    tgemm(p_hh, p_wfc2T, fc2_b, nullptr, nullptr, p_ah, T_, C_, 4 * C_, 0);
    // fused adapter + residual + unit-gamma LN -> fp16 z + fp16 xpat
    adapterln_kernel<<<T_, 128>>>(p_ah, ls2_g, ad_down_w, ad_down_b, ad_up_w, ad_up_b,
                                  xout, p_zh, p_xpat);

    cudaStreamWaitEvent(0, evB, 0);
    // all 6 view GEMMs in one launch (masked rows only, fp16 single pass, fp16 out)
    tgemm_views_kernel<<<dim3(3, TG_ / 128, V_), 256, SMEM_DYN>>>(p_zh, p_wattnT,
                                                                  p_bcorr, p_mcnt, p_mrows, p_hlocC);

    // batched gather-pool (warp per segment, fp16 in/out), BN stats, BN params
    gatherB_kernel<<<dim3((D2_ + 3) / 4, NSLOT_), 128>>>(p_xpat, p_hlocC, p_mpos, p_off, p_cnt,
                                                         p_list, p_tv, p_t3);
    seg_statsB_kernel<<<dim3(64, NSLOT_), C_>>>(p_tv, p_t3, p_stats);
    bnparam_kernel<<<NSLOT_, C_>>>(p_stats, bn2d_g, bn2d_b, bn3d_g, bn3d_b, p_bns, p_bnb);

    // cosine-weighted fusion (BN+gelu applied on the fly, fp16 tables)
    sims_kernel<<<(TG_ * 32 + 255) / 256, 256>>>(xout, cluster, fgi, p_t3, p_tv, p_bns, p_bnb);
}